// round 9
// baseline (speedup 1.0000x reference)
#include <cuda_runtime.h>
#include <cuda_bf16.h>

// ---------------- problem constants ----------------
constexpr int NN   = 50000;
constexpr int NE   = 512000;
constexpr int HD   = 128;
constexpr int EDIM = 32;
constexpr int NL   = 10;
constexpr int NG   = 64;
constexpr int NOUT = 10;
constexpr float EPSF  = 1e-5f;
constexpr float SLOPE = 0.2f;

typedef unsigned long long u64;
typedef unsigned int u32;

// ---------------- generic helpers ----------------
__device__ __forceinline__ float lrelu(float v) { return v < 0.f ? SLOPE * v : v; }
__device__ __forceinline__ u32 smem_u32(const void* p) {
    u32 a; asm("{ .reg .u64 t; cvta.to.shared.u64 t, %1; cvt.u32.u64 %0, t; }" : "=r"(a) : "l"(p));
    return a;
}
__device__ __forceinline__ u32 pack_bf2(float a, float b) {
    return (u32)__bfloat16_as_ushort(__float2bfloat16(a)) |
           ((u32)__bfloat16_as_ushort(__float2bfloat16(b)) << 16);
}
__device__ __forceinline__ float bf_lo(u32 v) {
    return __bfloat162float(__ushort_as_bfloat16((unsigned short)(v & 0xffff)));
}
__device__ __forceinline__ float bf_hi(u32 v) {
    return __bfloat162float(__ushort_as_bfloat16((unsigned short)(v >> 16)));
}

// ---------------- mma.sync helpers ----------------
__device__ __forceinline__ void ldsm_x4(u32* r, u32 addr) {
    asm volatile("ldmatrix.sync.aligned.m8n8.x4.shared.b16 {%0,%1,%2,%3}, [%4];"
                 : "=r"(r[0]), "=r"(r[1]), "=r"(r[2]), "=r"(r[3]) : "r"(addr));
}
__device__ __forceinline__ void ldsm_x2t(u32* r, u32 addr) {
    asm volatile("ldmatrix.sync.aligned.m8n8.x2.trans.shared.b16 {%0,%1}, [%2];"
                 : "=r"(r[0]), "=r"(r[1]) : "r"(addr));
}
__device__ __forceinline__ void mma16816(float* c, const u32* a, const u32* b) {
    asm volatile("mma.sync.aligned.m16n8k16.row.col.f32.bf16.bf16.f32 "
                 "{%0,%1,%2,%3}, {%4,%5,%6,%7}, {%8,%9}, {%0,%1,%2,%3};"
                 : "+f"(c[0]), "+f"(c[1]), "+f"(c[2]), "+f"(c[3])
                 : "r"(a[0]), "r"(a[1]), "r"(a[2]), "r"(a[3]), "r"(b[0]), "r"(b[1]));
}
__device__ __forceinline__ void cp_async16(u32 dst, const void* src) {
    asm volatile("cp.async.cg.shared.global [%0], [%1], 16;" :: "r"(dst), "l"(src));
}
__device__ __forceinline__ void cp_async_wait_all() {
    asm volatile("cp.async.commit_group;");
    asm volatile("cp.async.wait_group 0;" ::: "memory");
}

// ---------------- device scratch ----------------
__device__ __align__(16) u32   g_xb[NN * 64];           // x in packed bf16x2
__device__ __align__(16) u32   g_hfb[NN * 256];         // GAT features bf16x2
__device__ __align__(16) float g_agg[NN * HD];
__device__ __align__(16) float g_agg10[(size_t)NL * NN * HD];  // E10 terms
__device__ __align__(16) float g_t[NN * HD];
__device__ __align__(16) float g_o[NN * HD];
__device__ __align__(16) float g_x[NN * HD];
__device__ __align__(16) float g_eagg[NN * EDIM];
__device__           float g_u[NL * HD];
__device__           float g_degf[NN];
__device__           int   g_deg[NN];
__device__           int   g_rowptr[NN + 1];
__device__           int   g_cursor[NN];
__device__           int   g_csrc[NE];
__device__           int   g_ceid[NE];
__device__           int   g_bsum[64];
__device__           int   g_boff[64];
__device__ __align__(16) float g_as[NN * 4];
__device__ __align__(16) float g_ad[NN * 4];
__device__ __align__(16) float g_bnsum[HD];
__device__ __align__(16) float g_bnsq[HD];
__device__ __align__(16) float g_scale[HD];
__device__ __align__(16) float g_shift[HD];
__device__ __align__(16) float g_pool[NG * HD];

// Prepped weights: slots 0..9 WnW1[l] composite, 10..19 unused, 20..29 W2[l],
// 30..39 V[l]=We@W1 (rows 0..31 live), 40..43 Wg col blocks.
constexpr int NMAT = 44;
constexpr int WPAD = 136;
constexpr int WHALF = 128 * WPAD * 2;           // 34816
constexpr int WMAT_BYTES = 2 * WHALF;
__device__ __align__(16) char g_wb[(size_t)NMAT * WMAT_BYTES];

enum BufTag { T_NONE = 0, T_AGG, T_T, T_O, T_HFB };
__device__ __forceinline__ float* bufptr(int t) {
    switch (t) {
        case T_AGG:  return g_agg;
        case T_T:    return g_t;
        case T_O:    return g_o;
        default:     return nullptr;
    }
}

__device__ __forceinline__ void split_store(char* dst, int k, int n, float v) {
    __nv_bfloat16 h = __float2bfloat16(v);
    __nv_bfloat16 l = __float2bfloat16(v - __bfloat162float(h));
    ((__nv_bfloat16*)dst)[k * WPAD + n]           = h;
    ((__nv_bfloat16*)(dst + WHALF))[k * WPAD + n] = l;
}

// ---------------- weight prep: W2 and Wg slots ----------------
__global__ void prep_weights(const float* __restrict__ W2, const float* __restrict__ Wg) {
    int m = blockIdx.x;            // 0..13
    int slot = (m < 10) ? (20 + m) : (40 + (m - 10));
    char* dst = g_wb + (size_t)slot * WMAT_BYTES;
    for (int idx = threadIdx.x; idx < 16384; idx += blockDim.x) {
        int k = idx >> 7, n = idx & 127;
        float v = (m < 10) ? W2[(size_t)m * 16384 + k * 128 + n]
                           : Wg[(size_t)k * 512 + (m - 10) * 128 + n];
        split_store(dst, k, n, v);
    }
}

// ---------------- composite WnW1[l] = Wn[l] @ W1[l] ----------------
__global__ void comp_wnw1(const float* __restrict__ Wn, const float* __restrict__ W1) {
    extern __shared__ float s[];
    float* sA = s;           // Wn[l] 128x128
    float* sB = s + 16384;   // W1[l] 128x128
    int l = blockIdx.x, tid = threadIdx.x;
    const float* A = Wn + (size_t)l * 16384;
    const float* B = W1 + (size_t)l * 16384;
    for (int i = tid; i < 16384; i += 256) { sA[i] = A[i]; sB[i] = B[i]; }
    __syncthreads();
    char* dst = g_wb + (size_t)l * WMAT_BYTES;
    int k = tid >> 1, c0 = (tid & 1) * 64;
    for (int n = c0; n < c0 + 64; n++) {
        float acc = 0.f;
#pragma unroll 8
        for (int m = 0; m < 128; m++) acc += sA[k * 128 + m] * sB[m * 128 + n];
        split_store(dst, k, n, acc);
    }
}

// ---------------- composites V[l] = We[l]@W1[l], u[l] = (bnb+beb)@W1[l] ----------------
__global__ void comp_v(const float* __restrict__ We, const float* __restrict__ W1,
                       const float* __restrict__ bnb, const float* __restrict__ beb) {
    extern __shared__ float s[];
    float* sB  = s;            // W1[l] 16384
    float* sE  = s + 16384;    // We[l] 4096
    float* sbb = s + 20480;    // 128
    int l = blockIdx.x, tid = threadIdx.x;
    const float* B = W1 + (size_t)l * 16384;
    const float* E = We + (size_t)l * 4096;
    for (int i = tid; i < 16384; i += 256) sB[i] = B[i];
    for (int i = tid; i < 4096; i += 256) sE[i] = E[i];
    if (tid < 128) sbb[tid] = bnb[l * 128 + tid] + beb[l * 128 + tid];
    __syncthreads();
    char* dst = g_wb + (size_t)(30 + l) * WMAT_BYTES;
    int k = tid >> 3, c0 = (tid & 7) * 16;
    for (int n = c0; n < c0 + 16; n++) {
        float acc = 0.f;
#pragma unroll 8
        for (int m = 0; m < 128; m++) acc += sE[k * 128 + m] * sB[m * 128 + n];
        split_store(dst, k, n, acc);
    }
    if (tid < 128) {
        float acc = 0.f;
#pragma unroll 8
        for (int m = 0; m < 128; m++) acc += sbb[m] * sB[m * 128 + tid];
        g_u[l * 128 + tid] = acc;
    }
}

// ---------------- main tensor-core GEMM (M64xN128, dual-B resident, occ 2) ----------------
constexpr int AHALF = 64 * WPAD * 2;   // 17408
constexpr int SM_AH = 0;
constexpr int SM_AL = AHALF;
constexpr int SM_BH = 2 * AHALF;       // 34816
constexpr int SM_BL = 2 * AHALF + WHALF;
constexpr int SM_TOT = 2 * AHALF + 2 * WHALF;   // 104448 -> 2 CTAs/SM

template<bool RELU, bool NORM, bool STATS, bool OUTBF16, bool ADDC>
__global__ void __launch_bounds__(256, 2)
mma_gemm(const float* __restrict__ Aext, int Atag, int wmat,
         const float* __restrict__ bias, int Ctag, int ldc, int addl)
{
    extern __shared__ __align__(16) char smem[];
    u32 sb = smem_u32(smem);
    int tid = threadIdx.x, wid = tid >> 5, lane = tid & 31;
    int row0 = blockIdx.x * 64;
    int colb = blockIdx.y * 128;
    wmat += blockIdx.y;

    const float* A = Aext ? Aext : bufptr(Atag);
    float* C = bufptr(Ctag);
    const char* wsrc = g_wb + (size_t)wmat * WMAT_BYTES;

    // async copy B hi+lo (69632B)
    {
        const char* src = wsrc + tid * 16;
        u32 dst = sb + SM_BH + tid * 16;
#pragma unroll
        for (int i = 0; i < 17; i++)
            cp_async16(dst + i * 4096, src + i * 4096);
    }

    // load A tile (fp32), optional fused norm+relu, split to bf16 hi/lo
    {
        int r = tid >> 2, cb = (tid & 3) * 32;
        bool valid = (row0 + r) < NN;
        const float2* arow = (const float2*)(A + (size_t)(row0 + r) * 128 + cb);
        u32* AH = (u32*)(smem + SM_AH) + ((r * WPAD + cb) >> 1);
        u32* AL = (u32*)(smem + SM_AL) + ((r * WPAD + cb) >> 1);
#pragma unroll 8
        for (int i = 0; i < 16; i++) {
            float2 v = valid ? arow[i] : make_float2(0.f, 0.f);
            if (NORM) {
                float2 sc = *(const float2*)&g_scale[cb + 2 * i];
                float2 sh = *(const float2*)&g_shift[cb + 2 * i];
                v.x = fmaxf(v.x * sc.x + sh.x, 0.f);
                v.y = fmaxf(v.y * sc.y + sh.y, 0.f);
            }
            __nv_bfloat16 hx = __float2bfloat16(v.x), hy = __float2bfloat16(v.y);
            __nv_bfloat16 lx = __float2bfloat16(v.x - __bfloat162float(hx));
            __nv_bfloat16 ly = __float2bfloat16(v.y - __bfloat162float(hy));
            AH[i] = (u32)__bfloat16_as_ushort(hx) | ((u32)__bfloat16_as_ushort(hy) << 16);
            AL[i] = (u32)__bfloat16_as_ushort(lx) | ((u32)__bfloat16_as_ushort(ly) << 16);
        }
    }
    cp_async_wait_all();
    __syncthreads();

    int wm = wid >> 2, wn = wid & 3;

    float acc[2][4][4];
#pragma unroll
    for (int i = 0; i < 2; i++)
#pragma unroll
        for (int j = 0; j < 4; j++)
#pragma unroll
            for (int q = 0; q < 4; q++) acc[i][j][q] = 0.f;

    const u32 aoff[3] = { SM_AH, SM_AH, SM_AL };
    const u32 boff[3] = { SM_BH, SM_BL, SM_BH };

#pragma unroll
    for (int p = 0; p < 3; p++) {
        u32 sa0 = sb + aoff[p] + ((wm * 32 + (lane & 15)) * WPAD + (lane >> 4) * 8) * 2;
        u32 sb0 = sb + boff[p] + ((lane & 15) * WPAD + wn * 32) * 2;
#pragma unroll
        for (int k = 0; k < 8; k++) {
            u32 af[2][4];
#pragma unroll
            for (int i = 0; i < 2; i++)
                ldsm_x4(af[i], sa0 + i * 16 * (WPAD * 2) + k * 32);
            u32 bf[4][2];
#pragma unroll
            for (int j = 0; j < 4; j++)
                ldsm_x2t(bf[j], sb0 + k * 16 * (WPAD * 2) + j * 16);
#pragma unroll
            for (int i = 0; i < 2; i++)
#pragma unroll
                for (int j = 0; j < 4; j++)
                    mma16816(acc[i][j], af[i], bf[j]);
        }
    }

    // epilogue
    const float* EADD = ADDC ? (g_agg10 + (size_t)addl * NN * HD) : nullptr;
    float csum[8], csq[8];
    if (STATS) {
#pragma unroll
        for (int q = 0; q < 8; q++) { csum[q] = 0.f; csq[q] = 0.f; }
    }
#pragma unroll
    for (int i = 0; i < 2; i++) {
        int ra = row0 + wm * 32 + i * 16 + (lane >> 2);
#pragma unroll
        for (int half = 0; half < 2; half++) {
            int row = ra + half * 8;
            if (row < NN) {
#pragma unroll
                for (int j = 0; j < 4; j++) {
                    int cc = wn * 32 + j * 8 + (lane & 3) * 2;
                    float b0 = 0.f, b1 = 0.f;
                    if (bias) { b0 = bias[cc]; b1 = bias[cc + 1]; }
                    float v0 = acc[i][j][half * 2 + 0] + b0;
                    float v1 = acc[i][j][half * 2 + 1] + b1;
                    if (ADDC) {
                        float2 ev = *(const float2*)&EADD[(size_t)row * ldc + colb + cc];
                        v0 += ev.x; v1 += ev.y;
                    }
                    if (RELU) { v0 = fmaxf(v0, 0.f); v1 = fmaxf(v1, 0.f); }
                    if (STATS) {
                        csum[j * 2]     += v0; csq[j * 2]     += v0 * v0;
                        csum[j * 2 + 1] += v1; csq[j * 2 + 1] += v1 * v1;
                    }
                    if (OUTBF16) {
                        g_hfb[(size_t)row * (ldc >> 1) + ((colb + cc) >> 1)] = pack_bf2(v0, v1);
                    } else {
                        *(float2*)&C[(size_t)row * ldc + colb + cc] = make_float2(v0, v1);
                    }
                }
            }
        }
    }

    if (STATS) {
        float* ssum = (float*)smem;
        float* ssq  = ssum + 128;
        __syncthreads();
        if (tid < 128) { ssum[tid] = 0.f; ssq[tid] = 0.f; }
        __syncthreads();
#pragma unroll
        for (int j = 0; j < 4; j++) {
#pragma unroll
            for (int c = 0; c < 2; c++) {
                int col = wn * 32 + j * 8 + (lane & 3) * 2 + c;
                atomicAdd(&ssum[col], csum[j * 2 + c]);
                atomicAdd(&ssq[col],  csq[j * 2 + c]);
            }
        }
        __syncthreads();
        if (tid < 128) {
            atomicAdd(&g_bnsum[tid], ssum[tid]);
            atomicAdd(&g_bnsq[tid],  ssq[tid]);
        }
    }
}

// ---------------- batched E10 GEMM: g_agg10[l] = Eagg @ V[l] + deg*u[l] ----------------
constexpr int EPAD = 40;
constexpr int WE_AH = 0;
constexpr int WE_AL = 10240;
constexpr int WE_BH = 20480;
constexpr int WE_BL = 29184;
constexpr int WE_TOT = 37888;

__global__ void __launch_bounds__(256)
we_gemm()
{
    __shared__ __align__(16) char smem[WE_TOT];
    u32 sb = smem_u32(smem);
    int tid = threadIdx.x, wid = tid >> 5, lane = tid & 31;
    int row0 = blockIdx.x * 128;
    int l = blockIdx.y;

    {
        const char* mat = g_wb + (size_t)(30 + l) * WMAT_BYTES;
        for (int i = tid; i < 544; i += 256) {
            cp_async16(sb + WE_BH + i * 16, mat + i * 16);
            cp_async16(sb + WE_BL + i * 16, mat + WHALF + i * 16);
        }
    }
    {
        int r = tid >> 1, cb = (tid & 1) * 16;
        bool valid = (row0 + r) < NN;
        const float2* arow = (const float2*)(g_eagg + (size_t)(row0 + r) * 32 + cb);
        u32* AH = (u32*)(smem + WE_AH) + ((r * EPAD + cb) >> 1);
        u32* AL = (u32*)(smem + WE_AL) + ((r * EPAD + cb) >> 1);
#pragma unroll
        for (int i = 0; i < 8; i++) {
            float2 v = valid ? arow[i] : make_float2(0.f, 0.f);
            __nv_bfloat16 hx = __float2bfloat16(v.x), hy = __float2bfloat16(v.y);
            __nv_bfloat16 lx = __float2bfloat16(v.x - __bfloat162float(hx));
            __nv_bfloat16 ly = __float2bfloat16(v.y - __bfloat162float(hy));
            AH[i] = (u32)__bfloat16_as_ushort(hx) | ((u32)__bfloat16_as_ushort(hy) << 16);
            AL[i] = (u32)__bfloat16_as_ushort(lx) | ((u32)__bfloat16_as_ushort(ly) << 16);
        }
    }
    cp_async_wait_all();
    __syncthreads();

    int wm = wid >> 2, wn = wid & 3;
    float acc[4][4][4];
#pragma unroll
    for (int i = 0; i < 4; i++)
#pragma unroll
        for (int j = 0; j < 4; j++)
#pragma unroll
            for (int q = 0; q < 4; q++) acc[i][j][q] = 0.f;

    const u32 aoff[3] = { WE_AH, WE_AH, WE_AL };
    const u32 boff[3] = { WE_BH, WE_BL, WE_BH };
#pragma unroll
    for (int p = 0; p < 3; p++) {
        u32 sa0 = sb + aoff[p] + ((wm * 64 + (lane & 15)) * EPAD + (lane >> 4) * 8) * 2;
        u32 sb0 = sb + boff[p] + ((lane & 15) * WPAD + wn * 32) * 2;
#pragma unroll
        for (int k = 0; k < 2; k++) {
            u32 af[4][4];
#pragma unroll
            for (int i = 0; i < 4; i++)
                ldsm_x4(af[i], sa0 + i * 16 * (EPAD * 2) + k * 32);
            u32 bf[4][2];
#pragma unroll
            for (int j = 0; j < 4; j++)
                ldsm_x2t(bf[j], sb0 + k * 16 * (WPAD * 2) + j * 16);
#pragma unroll
            for (int i = 0; i < 4; i++)
#pragma unroll
                for (int j = 0; j < 4; j++)
                    mma16816(acc[i][j], af[i], bf[j]);
        }
    }

    float* C = g_agg10 + (size_t)l * NN * HD;
    const float* bias = g_u + l * HD;
#pragma unroll
    for (int i = 0; i < 4; i++) {
        int ra = row0 + wm * 64 + i * 16 + (lane >> 2);
#pragma unroll
        for (int half = 0; half < 2; half++) {
            int row = ra + half * 8;
            if (row < NN) {
                float rs = g_degf[row];
#pragma unroll
                for (int j = 0; j < 4; j++) {
                    int cc = wn * 32 + j * 8 + (lane & 3) * 2;
                    float v0 = acc[i][j][half * 2 + 0] + rs * bias[cc];
                    float v1 = acc[i][j][half * 2 + 1] + rs * bias[cc + 1];
                    *(float2*)&C[(size_t)row * HD + cc] = make_float2(v0, v1);
                }
            }
        }
    }
}

// ---------------- CSR build ----------------
__global__ void zero_deg() {
    int i = blockIdx.x * blockDim.x + threadIdx.x;
    if (i < NN) g_deg[i] = 0;
}
__global__ void hist_kernel(const int* __restrict__ ei) {
    int e = blockIdx.x * blockDim.x + threadIdx.x;
    if (e < NE) atomicAdd(&g_deg[ei[NE + e]], 1);
}
__global__ void scan_blocks() {
    __shared__ int wsum[32];
    int tid = threadIdx.x, lane = tid & 31, w = tid >> 5;
    int i = blockIdx.x * 1024 + tid;
    int v = (i < NN) ? g_deg[i] : 0;
    int x = v;
#pragma unroll
    for (int o = 1; o < 32; o <<= 1) { int t = __shfl_up_sync(~0u, x, o); if (lane >= o) x += t; }
    if (lane == 31) wsum[w] = x;
    __syncthreads();
    if (w == 0) {
        int s = wsum[lane];
#pragma unroll
        for (int o = 1; o < 32; o <<= 1) { int t = __shfl_up_sync(~0u, s, o); if (lane >= o) s += t; }
        wsum[lane] = s;
    }
    __syncthreads();
    int wexcl = (w == 0) ? 0 : wsum[w - 1];
    if (i < NN) g_rowptr[i] = wexcl + x - v;
    if (tid == 1023) g_bsum[blockIdx.x] = wsum[31];
}
__global__ void scan_tops() {
    int tid = threadIdx.x;
    __shared__ int sh[64];
    __shared__ int w0tot;
    int v = (tid < 49) ? g_bsum[tid] : 0;
    int lane = tid & 31, w = tid >> 5;
    int x = v;
#pragma unroll
    for (int o = 1; o < 32; o <<= 1) { int t = __shfl_up_sync(~0u, x, o); if (lane >= o) x += t; }
    if (w == 0 && lane == 31) w0tot = x;
    __syncthreads();
    int incl = x + (w == 1 ? w0tot : 0);
    sh[tid] = incl - v;
    __syncthreads();
    if (tid < 49) g_boff[tid] = sh[tid];
}
__global__ void scan_apply() {
    int i = blockIdx.x * blockDim.x + threadIdx.x;
    if (i >= NN) return;
    int rp = g_rowptr[i] + g_boff[i >> 10];
    g_rowptr[i] = rp;
    g_cursor[i] = rp;
    g_degf[i]   = (float)g_deg[i];
    if (i == 0) g_rowptr[NN] = NE;
}
__global__ void scatter_kernel(const int* __restrict__ ei) {
    int e = blockIdx.x * blockDim.x + threadIdx.x;
    if (e >= NE) return;
    int s = ei[e], d = ei[NE + e];
    int p = atomicAdd(&g_cursor[d], 1);
    g_csrc[p] = s;
    g_ceid[p] = e;
}
__global__ void eagg_kernel(const float* __restrict__ edge_attr) {
    int w = (blockIdx.x * blockDim.x + threadIdx.x) >> 5;
    if (w >= NN) return;
    int lane = threadIdx.x & 31;
    float acc = 0.f;
    int p0 = g_rowptr[w], p1 = g_rowptr[w + 1];
    for (int p = p0; p < p1; p++) {
        int e = g_ceid[p];
        acc += edge_attr[e * EDIM + lane];
    }
    g_eagg[w * EDIM + lane] = acc;
}

// ---------------- x conversion ----------------
__global__ void cvt_x(const float* __restrict__ x) {
    int i = blockIdx.x * blockDim.x + threadIdx.x;
    if (i >= NN * 64) return;
    float2 v = ((const float2*)x)[i];
    g_xb[i] = pack_bf2(v.x, v.y);
}
__global__ void normrelu_bf16() {
    int i = blockIdx.x * blockDim.x + threadIdx.x;
    if (i >= NN * 64) return;
    float2 v = ((const float2*)g_o)[i];
    int c = i & 63;
    float2 sc = ((const float2*)g_scale)[c];
    float2 sh = ((const float2*)g_shift)[c];
    float a = fmaxf(v.x * sc.x + sh.x, 0.f);
    float b = fmaxf(v.y * sc.y + sh.y, 0.f);
    g_xb[i] = pack_bf2(a, b);
}

// ---------------- gather: xagg[n] = sum x_bf16[src] ----------------
__global__ void gine_aggregate() {
    int w = (blockIdx.x * blockDim.x + threadIdx.x) >> 5;
    if (w >= NN) return;
    int lane = threadIdx.x & 31;
    float4 acc = { 0.f, 0.f, 0.f, 0.f };
    int p0 = g_rowptr[w], p1 = g_rowptr[w + 1];
    for (int p = p0; p < p1; p++) {
        int s = g_csrc[p];
        uint2 a = *(const uint2*)&g_xb[(size_t)s * 64 + lane * 2];
        acc.x += bf_lo(a.x); acc.y += bf_hi(a.x);
        acc.z += bf_lo(a.y); acc.w += bf_hi(a.y);
    }
    *(float4*)&g_agg[(size_t)w * HD + lane * 4] = acc;
}

// ---------------- BatchNorm scalars (self-resetting) ----------------
__global__ void bn_final(const float* __restrict__ gamma, const float* __restrict__ beta) {
    int c = threadIdx.x;
    if (c >= HD) return;
    float su = g_bnsum[c], sq = g_bnsq[c];
    g_bnsum[c] = 0.f;
    g_bnsq[c]  = 0.f;
    float mu  = su / (float)NN;
    float var = sq / (float)NN - mu * mu;
    float sc  = gamma[c] * rsqrtf(var + EPSF);
    g_scale[c] = sc;
    g_shift[c] = beta[c] - mu * sc;
}

// ---------------- GAT ----------------
__global__ void gat_node1(const float* __restrict__ att_src, const float* __restrict__ att_dst) {
    int n = (blockIdx.x * blockDim.x + threadIdx.x) >> 5;
    if (n >= NN) return;
    int lane = threadIdx.x & 31;
    float s[4], d[4];
#pragma unroll
    for (int h = 0; h < 4; h++) {
        uint2 hp = *(const uint2*)&g_hfb[(size_t)n * 256 + h * 64 + lane * 2];
        float4 hv = { bf_lo(hp.x), bf_hi(hp.x), bf_lo(hp.y), bf_hi(hp.y) };
        float4 a1 = *(const float4*)&att_src[h * 128 + lane * 4];
        float4 a2 = *(const float4*)&att_dst[h * 128 + lane * 4];
        float ps = hv.x * a1.x + hv.y * a1.y + hv.z * a1.z + hv.w * a1.w;
        float pd = hv.x * a2.x + hv.y * a2.y + hv.z * a2.z + hv.w * a2.w;
#pragma unroll
        for (int off = 16; off > 0; off >>= 1) {
            ps += __shfl_xor_sync(0xffffffffu, ps, off);
            pd += __shfl_xor_sync(0xffffffffu, pd, off);
        }
        s[h] = ps; d[h] = pd;
    }
    if (lane == 0) {
#pragma unroll
        for (int h = 0; h < 4; h++) {
            g_as[n * 4 + h] = s[h];
            g_ad[n * 4 + h] = d[h];
        }
    }
}
__global__ void gat_node_all(const float* __restrict__ bg) {
    int n = (blockIdx.x * blockDim.x + threadIdx.x) >> 5;
    if (n >= NN) return;
    int lane = threadIdx.x & 31;
    float4 asn = *(const float4*)&g_as[n * 4];
    float4 adn = *(const float4*)&g_ad[n * 4];
    float sl0 = lrelu(asn.x + adn.x), sl1 = lrelu(asn.y + adn.y);
    float sl2 = lrelu(asn.z + adn.z), sl3 = lrelu(asn.w + adn.w);
    int p0 = g_rowptr[n], p1 = g_rowptr[n + 1];

    float m0 = sl0, m1 = sl1, m2 = sl2, m3 = sl3;
    for (int p = p0 + lane; p < p1; p += 32) {
        float4 a = *(const float4*)&g_as[g_csrc[p] * 4];
        m0 = fmaxf(m0, lrelu(a.x + adn.x)); m1 = fmaxf(m1, lrelu(a.y + adn.y));
        m2 = fmaxf(m2, lrelu(a.z + adn.z)); m3 = fmaxf(m3, lrelu(a.w + adn.w));
    }
#pragma unroll
    for (int o = 16; o > 0; o >>= 1) {
        m0 = fmaxf(m0, __shfl_xor_sync(~0u, m0, o));
        m1 = fmaxf(m1, __shfl_xor_sync(~0u, m1, o));
        m2 = fmaxf(m2, __shfl_xor_sync(~0u, m2, o));
        m3 = fmaxf(m3, __shfl_xor_sync(~0u, m3, o));
    }
    float d0 = 0.f, d1 = 0.f, d2 = 0.f, d3 = 0.f;
    for (int p = p0 + lane; p < p1; p += 32) {
        float4 a = *(const float4*)&g_as[g_csrc[p] * 4];
        d0 += __expf(lrelu(a.x + adn.x) - m0); d1 += __expf(lrelu(a.y + adn.y) - m1);
        d2 += __expf(lrelu(a.z + adn.z) - m2); d3 += __expf(lrelu(a.w + adn.w) - m3);
    }
#pragma unroll
    for (int o = 16; o > 0; o >>= 1) {
        d0 += __shfl_xor_sync(~0u, d0, o); d1 += __shfl_xor_sync(~0u, d1, o);
        d2 += __shfl_xor_sync(~0u, d2, o); d3 += __shfl_xor_sync(~0u, d3, o);
    }
    d0 += __expf(sl0 - m0); d1 += __expf(sl1 - m1);
    d2 += __expf(sl2 - m2); d3 += __expf(sl3 - m3);
    float i0 = 1.f / d0, i1 = 1.f / d1, i2 = 1.f / d2, i3 = 1.f / d3;

    float w0 = __expf(sl0 - m0) * i0, w1 = __expf(sl1 - m1) * i1;
    float w2 = __expf(sl2 - m2) * i2, w3 = __expf(sl3 - m3) * i3;
    size_t base = (size_t)n * 256 + lane * 2;
    uint2 hp0 = *(const uint2*)&g_hfb[base];
    uint2 hp1 = *(const uint2*)&g_hfb[base + 64];
    uint2 hp2 = *(const uint2*)&g_hfb[base + 128];
    uint2 hp3 = *(const uint2*)&g_hfb[base + 192];
    float4 A0 = { w0 * bf_lo(hp0.x), w0 * bf_hi(hp0.x), w0 * bf_lo(hp0.y), w0 * bf_hi(hp0.y) };
    float4 A1 = { w1 * bf_lo(hp1.x), w1 * bf_hi(hp1.x), w1 * bf_lo(hp1.y), w1 * bf_hi(hp1.y) };
    float4 A2 = { w2 * bf_lo(hp2.x), w2 * bf_hi(hp2.x), w2 * bf_lo(hp2.y), w2 * bf_hi(hp2.y) };
    float4 A3 = { w3 * bf_lo(hp3.x), w3 * bf_hi(hp3.x), w3 * bf_lo(hp3.y), w3 * bf_hi(hp3.y) };
    for (int p = p0; p < p1; p++) {
        int s = g_csrc[p];
        float4 a = *(const float4*)&g_as[s * 4];
        float e0 = __expf(lrelu(a.x + adn.x) - m0) * i0;
        float e1 = __expf(lrelu(a.y + adn.y) - m1) * i1;
        float e2 = __expf(lrelu(a.z + adn.z) - m2) * i2;
        float e3 = __expf(lrelu(a.w + adn.w) - m3) * i3;
        size_t sbx = (size_t)s * 256 + lane * 2;
        uint2 v0 = *(const uint2*)&g_hfb[sbx];
        uint2 v1 = *(const uint2*)&g_hfb[sbx + 64];
        uint2 v2 = *(const uint2*)&g_hfb[sbx + 128];
        uint2 v3 = *(const uint2*)&g_hfb[sbx + 192];
        A0.x += e0 * bf_lo(v0.x); A0.y += e0 * bf_hi(v0.x); A0.z += e0 * bf_lo(v0.y); A0.w += e0 * bf_hi(v0.y);
        A1.x += e1 * bf_lo(v1.x); A1.y += e1 * bf_hi(v1.x); A1.z += e1 * bf_lo(v1.y); A1.w += e1 * bf_hi(v1.y);
        A2.x += e2 * bf_lo(v2.x); A2.y += e2 * bf_hi(v2.x); A2.z += e2 * bf_lo(v2.y); A2.w += e2 * bf_hi(v2.y);
        A3.x += e3 * bf_lo(v3.x); A3.y += e3 * bf_hi(v3.x); A3.z += e3 * bf_lo(v3.y); A3.w += e3 * bf_hi(v3.y);
    }
    float4 bg4 = *(const float4*)&bg[lane * 4];
    float4 o4;
    o4.x = (A0.x + A1.x + A2.x + A3.x) * 0.25f + bg4.x;
    o4.y = (A0.y + A1.y + A2.y + A3.y) * 0.25f + bg4.y;
    o4.z = (A0.z + A1.z + A2.z + A3.z) * 0.25f + bg4.z;
    o4.w = (A0.w + A1.w + A2.w + A3.w) * 0.25f + bg4.w;
    *(float4*)&g_x[(size_t)n * HD + lane * 4] = o4;
}

// ---------------- pooling + fc ----------------
__device__ __forceinline__ int lbound(const int* a, int n, int key) {
    int lo = 0, hi = n;
    while (lo < hi) { int mid = (lo + hi) >> 1; if (a[mid] < key) lo = mid + 1; else hi = mid; }
    return lo;
}
__global__ void pool_kernel(const int* __restrict__ batch) {
    int g = blockIdx.x;
    int c = threadIdx.x;
    __shared__ int slo, shi;
    if (c == 0) { slo = lbound(batch, NN, g); shi = lbound(batch, NN, g + 1); }
    __syncthreads();
    int lo = slo, hi = shi;
    float a0 = 0.f, a1 = 0.f, a2 = 0.f, a3 = 0.f;
    int n = lo;
    for (; n + 4 <= hi; n += 4) {
        a0 += g_x[(size_t)n * HD + c];
        a1 += g_x[(size_t)(n + 1) * HD + c];
        a2 += g_x[(size_t)(n + 2) * HD + c];
        a3 += g_x[(size_t)(n + 3) * HD + c];
    }
    for (; n < hi; n++) a0 += g_x[(size_t)n * HD + c];
    float s = (a0 + a1) + (a2 + a3);
    g_pool[g * HD + c] = s / fmaxf((float)(hi - lo), 1.f);
}
__global__ void final_kernel(const float* __restrict__ Wfc, const float* __restrict__ bfc,
                             float* __restrict__ out) {
    int idx = blockIdx.x * blockDim.x + threadIdx.x;
    if (idx >= NG * NOUT) return;
    int g = idx / NOUT, o = idx % NOUT;
    float s = bfc[o];
#pragma unroll 8
    for (int k = 0; k < HD; k++) s += g_pool[g * HD + k] * Wfc[k * NOUT + o];
    out[idx] = s;
}

// ---------------- driver ----------------
extern "C" void kernel_launch(void* const* d_in, const int* in_sizes, int n_in,
                              void* d_out, int out_size) {
    const float* x_in      = (const float*)d_in[0];
    const float* edge_attr = (const float*)d_in[1];
    const int*   ei        = (const int*)d_in[2];
    const int*   batch     = (const int*)d_in[3];
    const float* Wn   = (const float*)d_in[4];
    const float* bn_b = (const float*)d_in[5];
    const float* We   = (const float*)d_in[6];
    const float* be_b = (const float*)d_in[7];
    const float* W1   = (const float*)d_in[8];
    const float* b1   = (const float*)d_in[9];
    const float* W2   = (const float*)d_in[10];
    const float* b2   = (const float*)d_in[11];
    const float* gamma= (const float*)d_in[12];
    const float* beta = (const float*)d_in[13];
    const float* Wg   = (const float*)d_in[14];
    const float* att_src = (const float*)d_in[15];
    const float* att_dst = (const float*)d_in[16];
    const float* bg   = (const float*)d_in[17];
    const float* Wfc  = (const float*)d_in[18];
    const float* bfc  = (const float*)d_in[19];
    float* out = (float*)d_out;

    cudaFuncSetAttribute(mma_gemm<true ,false,false,false,true >, cudaFuncAttributeMaxDynamicSharedMemorySize, SM_TOT);
    cudaFuncSetAttribute(mma_gemm<false,false,true ,false,false>, cudaFuncAttributeMaxDynamicSharedMemorySize, SM_TOT);
    cudaFuncSetAttribute(mma_gemm<false,true ,false,true ,false>, cudaFuncAttributeMaxDynamicSharedMemorySize, SM_TOT);
    cudaFuncSetAttribute(comp_wnw1, cudaFuncAttributeMaxDynamicSharedMemorySize, 131072);
    cudaFuncSetAttribute(comp_v,    cudaFuncAttributeMaxDynamicSharedMemorySize, 83968);

    const int TB = 256;
    const int NODE_BLK = (NN + TB - 1) / TB;
    const int EDGE_BLK = (NE + TB - 1) / TB;
    const int WARP_BLK = (NN * 32 + TB - 1) / TB;
    const int VEC_BLK  = (NN * 64 + TB - 1) / TB;
    const dim3 GEMM_G(782, 1);
    const dim3 GEMM_G4(782, 4);

    // prologue
    prep_weights<<<14, 256>>>(W2, Wg);                               // 0
    comp_wnw1<<<10, 256, 131072>>>(Wn, W1);                          // 1
    comp_v<<<10, 256, 83968>>>(We, W1, bn_b, be_b);                  // 2
    cvt_x<<<VEC_BLK, TB>>>(x_in);                                    // 3
    zero_deg<<<NODE_BLK, TB>>>();                                    // 4
    hist_kernel<<<EDGE_BLK, TB>>>(ei);                               // 5
    scan_blocks<<<49, 1024>>>();                                     // 6
    scan_tops<<<1, 64>>>();                                          // 7
    scan_apply<<<NODE_BLK, TB>>>();                                  // 8
    scatter_kernel<<<EDGE_BLK, TB>>>(ei);                            // 9
    eagg_kernel<<<WARP_BLK, TB>>>(edge_attr);                        // 10
    we_gemm<<<dim3(391, 10), 256>>>();                               // 11

    // ---- 10 GINE layers (2 GEMMs each) ----
    for (int l = 0; l < NL; l++) {
        if (l > 0) normrelu_bf16<<<VEC_BLK, TB>>>();
        gine_aggregate<<<WARP_BLK, TB>>>();
        // t = relu(xagg @ WnW1[l] + E10[l] + b1)
        mma_gemm<true ,false,false,false,true ><<<GEMM_G, 256, SM_TOT>>>(
            nullptr, T_AGG, l, b1 + l * HD, T_T, HD, l);
        // o = t @ W2[l] + b2, fused BN stats
        mma_gemm<false,false,true ,false,false><<<GEMM_G, 256, SM_TOT>>>(
            nullptr, T_T, 20 + l, b2 + l * HD, T_O, HD, 0);
        bn_final<<<1, 128>>>(gamma + l * HD, beta + l * HD);
    }

    // ---- GAT (A-load applies layer-9 norm+relu; bf16 features out) ----
    mma_gemm<false,true ,false,true ,false><<<GEMM_G4, 256, SM_TOT>>>(
        nullptr, T_O, 40, nullptr, T_HFB, 512, 0);
    gat_node1<<<WARP_BLK, TB>>>(att_src, att_dst);
    gat_node_all<<<WARP_BLK, TB>>>(bg);

    // ---- pool + fc ----
    pool_kernel<<<NG, 128>>>(batch);
    final_kernel<<<(NG * NOUT + TB - 1) / TB, TB>>>(Wfc, bfc, out);
}

// round 13
// speedup vs baseline: 1.1928x; 1.1928x over previous
#include <cuda_runtime.h>
#include <cuda_bf16.h>

// ---------------- problem constants ----------------
constexpr int NN   = 50000;
constexpr int NE   = 512000;
constexpr int HD   = 128;
constexpr int EDIM = 32;
constexpr int NL   = 10;
constexpr int NG   = 64;
constexpr int NOUT = 10;
constexpr float EPSF  = 1e-5f;
constexpr float SLOPE = 0.2f;

typedef unsigned long long u64;
typedef unsigned int u32;

// ---------------- generic helpers ----------------
__device__ __forceinline__ float lrelu(float v) { return v < 0.f ? SLOPE * v : v; }
__device__ __forceinline__ u32 smem_u32(const void* p) {
    u32 a; asm("{ .reg .u64 t; cvta.to.shared.u64 t, %1; cvt.u32.u64 %0, t; }" : "=r"(a) : "l"(p));
    return a;
}
__device__ __forceinline__ u32 pack_bf2(float a, float b) {
    return (u32)__bfloat16_as_ushort(__float2bfloat16(a)) |
           ((u32)__bfloat16_as_ushort(__float2bfloat16(b)) << 16);
}
__device__ __forceinline__ float bf_lo(u32 v) {
    return __bfloat162float(__ushort_as_bfloat16((unsigned short)(v & 0xffff)));
}
__device__ __forceinline__ float bf_hi(u32 v) {
    return __bfloat162float(__ushort_as_bfloat16((unsigned short)(v >> 16)));
}

// ---------------- mma.sync helpers ----------------
__device__ __forceinline__ void ldsm_x4(u32* r, u32 addr) {
    asm volatile("ldmatrix.sync.aligned.m8n8.x4.shared.b16 {%0,%1,%2,%3}, [%4];"
                 : "=r"(r[0]), "=r"(r[1]), "=r"(r[2]), "=r"(r[3]) : "r"(addr));
}
__device__ __forceinline__ void ldsm_x2t(u32* r, u32 addr) {
    asm volatile("ldmatrix.sync.aligned.m8n8.x2.trans.shared.b16 {%0,%1}, [%2];"
                 : "=r"(r[0]), "=r"(r[1]) : "r"(addr));
}
__device__ __forceinline__ void mma16816(float* c, const u32* a, const u32* b) {
    asm volatile("mma.sync.aligned.m16n8k16.row.col.f32.bf16.bf16.f32 "
                 "{%0,%1,%2,%3}, {%4,%5,%6,%7}, {%8,%9}, {%0,%1,%2,%3};"
                 : "+f"(c[0]), "+f"(c[1]), "+f"(c[2]), "+f"(c[3])
                 : "r"(a[0]), "r"(a[1]), "r"(a[2]), "r"(a[3]), "r"(b[0]), "r"(b[1]));
}
__device__ __forceinline__ void cp_async16(u32 dst, const void* src) {
    asm volatile("cp.async.cg.shared.global [%0], [%1], 16;" :: "r"(dst), "l"(src));
}
__device__ __forceinline__ void cp_async_wait_all() {
    asm volatile("cp.async.commit_group;");
    asm volatile("cp.async.wait_group 0;" ::: "memory");
}

// ---------------- device scratch ----------------
__device__ __align__(16) u32   g_xb[NN * 64];           // x packed bf16x2
__device__ __align__(16) u32   g_aggb[NN * 64];         // gathered sum, bf16x2
__device__ __align__(16) u32   g_tb[NN * 64];           // t, bf16x2
__device__ __align__(16) u32   g_hfb[NN * 256];         // GAT features bf16x2
__device__ __align__(16) float g_agg10[(size_t)NL * NN * HD];  // E10 terms
__device__ __align__(16) float g_o[NN * HD];
__device__ __align__(16) float g_x[NN * HD];
__device__ __align__(16) float g_eagg[NN * EDIM];
__device__           float g_u[NL * HD];
__device__           float g_degf[NN];
__device__           int   g_deg[NN];
__device__           int   g_rowptr[NN + 1];
__device__           int   g_cursor[NN];
__device__           int   g_csrc[NE];
__device__           int   g_ceid[NE];
__device__           int   g_bsum[64];
__device__           int   g_boff[64];
__device__ __align__(16) float g_as[NN * 4];
__device__ __align__(16) float g_ad[NN * 4];
__device__ __align__(16) float g_bnsum[HD];
__device__ __align__(16) float g_bnsq[HD];
__device__ __align__(16) float g_scale[HD];
__device__ __align__(16) float g_shift[HD];
__device__ __align__(16) float g_pool[NG * HD];

// Prepped weights: 0..9 WnW1[l], 20..29 W2[l], 30..39 V[l]=We@W1, 40..43 Wg blocks.
constexpr int NMAT = 44;
constexpr int WPAD = 136;
constexpr int WHALF = 128 * WPAD * 2;           // 34816
constexpr int WMAT_BYTES = 2 * WHALF;
__device__ __align__(16) char g_wb[(size_t)NMAT * WMAT_BYTES];

enum UTag { U_AGGB = 1, U_TB, U_HFB };
__device__ __forceinline__ u32* ubuf(int t) {
    switch (t) {
        case U_AGGB: return g_aggb;
        case U_TB:   return g_tb;
        case U_HFB:  return g_hfb;
        default:     return nullptr;
    }
}

__device__ __forceinline__ void split_store(char* dst, int k, int n, float v) {
    __nv_bfloat16 h = __float2bfloat16(v);
    __nv_bfloat16 l = __float2bfloat16(v - __bfloat162float(h));
    ((__nv_bfloat16*)dst)[k * WPAD + n]           = h;
    ((__nv_bfloat16*)(dst + WHALF))[k * WPAD + n] = l;
}

// ---------------- weight prep ----------------
__global__ void prep_weights(const float* __restrict__ W2, const float* __restrict__ Wg) {
    int m = blockIdx.x;            // 0..13
    int slot = (m < 10) ? (20 + m) : (40 + (m - 10));
    char* dst = g_wb + (size_t)slot * WMAT_BYTES;
    for (int idx = threadIdx.x; idx < 16384; idx += blockDim.x) {
        int k = idx >> 7, n = idx & 127;
        float v = (m < 10) ? W2[(size_t)m * 16384 + k * 128 + n]
                           : Wg[(size_t)k * 512 + (m - 10) * 128 + n];
        split_store(dst, k, n, v);
    }
}
__global__ void comp_wnw1(const float* __restrict__ Wn, const float* __restrict__ W1) {
    extern __shared__ float s[];
    float* sA = s;
    float* sB = s + 16384;
    int l = blockIdx.x, tid = threadIdx.x;
    const float* A = Wn + (size_t)l * 16384;
    const float* B = W1 + (size_t)l * 16384;
    for (int i = tid; i < 16384; i += 256) { sA[i] = A[i]; sB[i] = B[i]; }
    __syncthreads();
    char* dst = g_wb + (size_t)l * WMAT_BYTES;
    int k = tid >> 1, c0 = (tid & 1) * 64;
    for (int n = c0; n < c0 + 64; n++) {
        float acc = 0.f;
#pragma unroll 8
        for (int m = 0; m < 128; m++) acc += sA[k * 128 + m] * sB[m * 128 + n];
        split_store(dst, k, n, acc);
    }
}
__global__ void comp_v(const float* __restrict__ We, const float* __restrict__ W1,
                       const float* __restrict__ bnb, const float* __restrict__ beb) {
    extern __shared__ float s[];
    float* sB  = s;
    float* sE  = s + 16384;
    float* sbb = s + 20480;
    int l = blockIdx.x, tid = threadIdx.x;
    const float* B = W1 + (size_t)l * 16384;
    const float* E = We + (size_t)l * 4096;
    for (int i = tid; i < 16384; i += 256) sB[i] = B[i];
    for (int i = tid; i < 4096; i += 256) sE[i] = E[i];
    if (tid < 128) sbb[tid] = bnb[l * 128 + tid] + beb[l * 128 + tid];
    __syncthreads();
    char* dst = g_wb + (size_t)(30 + l) * WMAT_BYTES;
    int k = tid >> 3, c0 = (tid & 7) * 16;
    for (int n = c0; n < c0 + 16; n++) {
        float acc = 0.f;
#pragma unroll 8
        for (int m = 0; m < 128; m++) acc += sE[k * 128 + m] * sB[m * 128 + n];
        split_store(dst, k, n, acc);
    }
    if (tid < 128) {
        float acc = 0.f;
#pragma unroll 8
        for (int m = 0; m < 128; m++) acc += sbb[m] * sB[m * 128 + tid];
        g_u[l * 128 + tid] = acc;
    }
}

// ---------------- main GEMM: bf16x2 (A single bf16, W = Wh+Wl), M64xN128, occ 2 ----------------
constexpr int AHALF = 64 * WPAD * 2;   // 17408 (single A buffer)
constexpr int SM_A  = 0;
constexpr int SM_BH = AHALF;           // 17408
constexpr int SM_BL = AHALF + WHALF;   // 52224
constexpr int SM_TOT = AHALF + 2 * WHALF;   // 87040 -> 2 CTAs/SM

// RELU / NORM(fp32 A, uses g_scale/g_shift) / STATS / OUTBF16 / ADDC / ABF16
template<bool RELU, bool NORM, bool STATS, bool OUTBF16, bool ADDC, bool ABF16>
__global__ void __launch_bounds__(256, 2)
mma_gemm(const float* __restrict__ Afp, int autag, int wmat,
         const float* __restrict__ bias, int Ctag, int ldc, int addl)
{
    extern __shared__ __align__(16) char smem[];
    u32 sb = smem_u32(smem);
    int tid = threadIdx.x, wid = tid >> 5, lane = tid & 31;
    int row0 = blockIdx.x * 64;
    int colb = blockIdx.y * 128;
    wmat += blockIdx.y;

    const char* wsrc = g_wb + (size_t)wmat * WMAT_BYTES;

    // async copy B hi+lo (69632B)
    {
        const char* src = wsrc + tid * 16;
        u32 dst = sb + SM_BH + tid * 16;
#pragma unroll
        for (int i = 0; i < 17; i++)
            cp_async16(dst + i * 4096, src + i * 4096);
    }

    // load A tile -> single bf16 in SMEM
    {
        int r = tid >> 2, cb = (tid & 3) * 32;
        bool valid = (row0 + r) < NN;
        u32* AS = (u32*)(smem + SM_A) + ((r * WPAD + cb) >> 1);
        if (ABF16) {
            const u32* arow = ubuf(autag) + (size_t)(row0 + r) * 64 + (cb >> 1);
#pragma unroll
            for (int i = 0; i < 16; i++)
                AS[i] = valid ? arow[i] : 0u;
        } else {
            const float* A = Afp ? Afp : g_o;     // device-side fallback (no host symbol ref)
            const float2* arow = (const float2*)(A + (size_t)(row0 + r) * 128 + cb);
#pragma unroll 8
            for (int i = 0; i < 16; i++) {
                float2 v = valid ? arow[i] : make_float2(0.f, 0.f);
                if (NORM) {
                    float2 sc = *(const float2*)&g_scale[cb + 2 * i];
                    float2 sh = *(const float2*)&g_shift[cb + 2 * i];
                    v.x = fmaxf(v.x * sc.x + sh.x, 0.f);
                    v.y = fmaxf(v.y * sc.y + sh.y, 0.f);
                }
                AS[i] = pack_bf2(v.x, v.y);
            }
        }
    }
    cp_async_wait_all();
    __syncthreads();

    int wm = wid >> 2, wn = wid & 3;

    float acc[2][4][4];
#pragma unroll
    for (int i = 0; i < 2; i++)
#pragma unroll
        for (int j = 0; j < 4; j++)
#pragma unroll
            for (int q = 0; q < 4; q++) acc[i][j][q] = 0.f;

    const u32 boff[2] = { SM_BH, SM_BL };
#pragma unroll
    for (int p = 0; p < 2; p++) {
        u32 sa0 = sb + SM_A + ((wm * 32 + (lane & 15)) * WPAD + (lane >> 4) * 8) * 2;
        u32 sb0 = sb + boff[p] + ((lane & 15) * WPAD + wn * 32) * 2;
#pragma unroll
        for (int k = 0; k < 8; k++) {
            u32 af[2][4];
#pragma unroll
            for (int i = 0; i < 2; i++)
                ldsm_x4(af[i], sa0 + i * 16 * (WPAD * 2) + k * 32);
            u32 bf[4][2];
#pragma unroll
            for (int j = 0; j < 4; j++)
                ldsm_x2t(bf[j], sb0 + k * 16 * (WPAD * 2) + j * 16);
#pragma unroll
            for (int i = 0; i < 2; i++)
#pragma unroll
                for (int j = 0; j < 4; j++)
                    mma16816(acc[i][j], af[i], bf[j]);
        }
    }

    // epilogue
    const float* EADD = ADDC ? (g_agg10 + (size_t)addl * NN * HD) : nullptr;
    float csum[8], csq[8];
    if (STATS) {
#pragma unroll
        for (int q = 0; q < 8; q++) { csum[q] = 0.f; csq[q] = 0.f; }
    }
#pragma unroll
    for (int i = 0; i < 2; i++) {
        int ra = row0 + wm * 32 + i * 16 + (lane >> 2);
#pragma unroll
        for (int half = 0; half < 2; half++) {
            int row = ra + half * 8;
            if (row < NN) {
#pragma unroll
                for (int j = 0; j < 4; j++) {
                    int cc = wn * 32 + j * 8 + (lane & 3) * 2;
                    float b0 = 0.f, b1 = 0.f;
                    if (bias) { b0 = bias[cc]; b1 = bias[cc + 1]; }
                    float v0 = acc[i][j][half * 2 + 0] + b0;
                    float v1 = acc[i][j][half * 2 + 1] + b1;
                    if (ADDC) {
                        float2 ev = *(const float2*)&EADD[(size_t)row * HD + cc];
                        v0 += ev.x; v1 += ev.y;
                    }
                    if (RELU) { v0 = fmaxf(v0, 0.f); v1 = fmaxf(v1, 0.f); }
                    if (STATS) {
                        csum[j * 2]     += v0; csq[j * 2]     += v0 * v0;
                        csum[j * 2 + 1] += v1; csq[j * 2 + 1] += v1 * v1;
                    }
                    if (OUTBF16) {
                        ubuf(Ctag)[(size_t)row * (ldc >> 1) + ((colb + cc) >> 1)] = pack_bf2(v0, v1);
                    } else {
                        *(float2*)&g_o[(size_t)row * HD + cc] = make_float2(v0, v1);
                    }
                }
            }
        }
    }

    if (STATS) {
        float* ssum = (float*)smem;
        float* ssq  = ssum + 128;
        __syncthreads();
        if (tid < 128) { ssum[tid] = 0.f; ssq[tid] = 0.f; }
        __syncthreads();
#pragma unroll
        for (int j = 0; j < 4; j++) {
#pragma unroll
            for (int c = 0; c < 2; c++) {
                int col = wn * 32 + j * 8 + (lane & 3) * 2 + c;
                atomicAdd(&ssum[col], csum[j * 2 + c]);
                atomicAdd(&ssq[col],  csq[j * 2 + c]);
            }
        }
        __syncthreads();
        if (tid < 128) {
            atomicAdd(&g_bnsum[tid], ssum[tid]);
            atomicAdd(&g_bnsq[tid],  ssq[tid]);
        }
    }
}

// ---------------- batched E10 GEMM (2-pass): g_agg10[l] = Eagg @ V[l] + deg*u[l] ----------------
constexpr int EPAD = 40;
constexpr int WE_A  = 0;        // 128*40*2 = 10240
constexpr int WE_BH = 10240;    // 8704
constexpr int WE_BL = 18944;
constexpr int WE_TOT = 27648;

__global__ void __launch_bounds__(256)
we_gemm()
{
    __shared__ __align__(16) char smem[WE_TOT];
    u32 sb = smem_u32(smem);
    int tid = threadIdx.x, wid = tid >> 5, lane = tid & 31;
    int row0 = blockIdx.x * 128;
    int l = blockIdx.y;

    {
        const char* mat = g_wb + (size_t)(30 + l) * WMAT_BYTES;
        for (int i = tid; i < 544; i += 256) {
            cp_async16(sb + WE_BH + i * 16, mat + i * 16);
            cp_async16(sb + WE_BL + i * 16, mat + WHALF + i * 16);
        }
    }
    {
        int r = tid >> 1, cb = (tid & 1) * 16;
        bool valid = (row0 + r) < NN;
        const float2* arow = (const float2*)(g_eagg + (size_t)(row0 + r) * 32 + cb);
        u32* AS = (u32*)(smem + WE_A) + ((r * EPAD + cb) >> 1);
#pragma unroll
        for (int i = 0; i < 8; i++) {
            float2 v = valid ? arow[i] : make_float2(0.f, 0.f);
            AS[i] = pack_bf2(v.x, v.y);
        }
    }
    cp_async_wait_all();
    __syncthreads();

    int wm = wid >> 2, wn = wid & 3;
    float acc[4][4][4];
#pragma unroll
    for (int i = 0; i < 4; i++)
#pragma unroll
        for (int j = 0; j < 4; j++)
#pragma unroll
            for (int q = 0; q < 4; q++) acc[i][j][q] = 0.f;

    const u32 boff[2] = { WE_BH, WE_BL };
#pragma unroll
    for (int p = 0; p < 2; p++) {
        u32 sa0 = sb + WE_A + ((wm * 64 + (lane & 15)) * EPAD + (lane >> 4) * 8) * 2;
        u32 sb0 = sb + boff[p] + ((lane & 15) * WPAD + wn * 32) * 2;
#pragma unroll
        for (int k = 0; k < 2; k++) {
            u32 af[4][4];
#pragma unroll
            for (int i = 0; i < 4; i++)
                ldsm_x4(af[i], sa0 + i * 16 * (EPAD * 2) + k * 32);
            u32 bf[4][2];
#pragma unroll
            for (int j = 0; j < 4; j++)
                ldsm_x2t(bf[j], sb0 + k * 16 * (WPAD * 2) + j * 16);
#pragma unroll
            for (int i = 0; i < 4; i++)
#pragma unroll
                for (int j = 0; j < 4; j++)
                    mma16816(acc[i][j], af[i], bf[j]);
        }
    }

    float* C = g_agg10 + (size_t)l * NN * HD;
    const float* bias = g_u + l * HD;
#pragma unroll
    for (int i = 0; i < 4; i++) {
        int ra = row0 + wm * 64 + i * 16 + (lane >> 2);
#pragma unroll
        for (int half = 0; half < 2; half++) {
            int row = ra + half * 8;
            if (row < NN) {
                float rs = g_degf[row];
#pragma unroll
                for (int j = 0; j < 4; j++) {
                    int cc = wn * 32 + j * 8 + (lane & 3) * 2;
                    float v0 = acc[i][j][half * 2 + 0] + rs * bias[cc];
                    float v1 = acc[i][j][half * 2 + 1] + rs * bias[cc + 1];
                    *(float2*)&C[(size_t)row * HD + cc] = make_float2(v0, v1);
                }
            }
        }
    }
}

// ---------------- CSR build ----------------
__global__ void zero_deg() {
    int i = blockIdx.x * blockDim.x + threadIdx.x;
    if (i < NN) g_deg[i] = 0;
    if (i < HD) { g_bnsum[i] = 0.f; g_bnsq[i] = 0.f; }
}
__global__ void hist_kernel(const int* __restrict__ ei) {
    int e = blockIdx.x * blockDim.x + threadIdx.x;
    if (e < NE) atomicAdd(&g_deg[ei[NE + e]], 1);
}
__global__ void scan_blocks() {
    __shared__ int wsum[32];
    int tid = threadIdx.x, lane = tid & 31, w = tid >> 5;
    int i = blockIdx.x * 1024 + tid;
    int v = (i < NN) ? g_deg[i] : 0;
    int x = v;
#pragma unroll
    for (int o = 1; o < 32; o <<= 1) { int t = __shfl_up_sync(~0u, x, o); if (lane >= o) x += t; }
    if (lane == 31) wsum[w] = x;
    __syncthreads();
    if (w == 0) {
        int s = wsum[lane];
#pragma unroll
        for (int o = 1; o < 32; o <<= 1) { int t = __shfl_up_sync(~0u, s, o); if (lane >= o) s += t; }
        wsum[lane] = s;
    }
    __syncthreads();
    int wexcl = (w == 0) ? 0 : wsum[w - 1];
    if (i < NN) g_rowptr[i] = wexcl + x - v;
    if (tid == 1023) g_bsum[blockIdx.x] = wsum[31];
}
__global__ void scan_tops() {
    int tid = threadIdx.x;
    __shared__ int sh[64];
    __shared__ int w0tot;
    int v = (tid < 49) ? g_bsum[tid] : 0;
    int lane = tid & 31, w = tid >> 5;
    int x = v;
#pragma unroll
    for (int o = 1; o < 32; o <<= 1) { int t = __shfl_up_sync(~0u, x, o); if (lane >= o) x += t; }
    if (w == 0 && lane == 31) w0tot = x;
    __syncthreads();
    int incl = x + (w == 1 ? w0tot : 0);
    sh[tid] = incl - v;
    __syncthreads();
    if (tid < 49) g_boff[tid] = sh[tid];
}
__global__ void scan_apply() {
    int i = blockIdx.x * blockDim.x + threadIdx.x;
    if (i >= NN) return;
    int rp = g_rowptr[i] + g_boff[i >> 10];
    g_rowptr[i] = rp;
    g_cursor[i] = rp;
    g_degf[i]   = (float)g_deg[i];
    if (i == 0) g_rowptr[NN] = NE;
}
__global__ void scatter_kernel(const int* __restrict__ ei) {
    int e = blockIdx.x * blockDim.x + threadIdx.x;
    if (e >= NE) return;
    int s = ei[e], d = ei[NE + e];
    int p = atomicAdd(&g_cursor[d], 1);
    g_csrc[p] = s;
    g_ceid[p] = e;
}
__global__ void eagg_kernel(const float* __restrict__ edge_attr) {
    int w = (blockIdx.x * blockDim.x + threadIdx.x) >> 5;
    if (w >= NN) return;
    int lane = threadIdx.x & 31;
    float acc = 0.f;
    int p0 = g_rowptr[w], p1 = g_rowptr[w + 1];
    for (int p = p0; p < p1; p++) {
        int e = g_ceid[p];
        acc += edge_attr[e * EDIM + lane];
    }
    g_eagg[w * EDIM + lane] = acc;
}

// ---------------- conversions ----------------
__global__ void cvt_x(const float* __restrict__ x) {
    int i = blockIdx.x * blockDim.x + threadIdx.x;
    if (i >= NN * 64) return;
    float2 v = ((const float2*)x)[i];
    g_xb[i] = pack_bf2(v.x, v.y);
}
__global__ void normrelu_bf16() {
    int i = blockIdx.x * blockDim.x + threadIdx.x;
    if (i >= NN * 64) return;
    float2 v = ((const float2*)g_o)[i];
    int c = i & 63;
    float2 sc = ((const float2*)g_scale)[c];
    float2 sh = ((const float2*)g_shift)[c];
    float a = fmaxf(v.x * sc.x + sh.x, 0.f);
    float b = fmaxf(v.y * sc.y + sh.y, 0.f);
    g_xb[i] = pack_bf2(a, b);
}

// ---------------- gather: aggb[n] = sum x_bf16[src] (bf16 out) ----------------
__global__ void gine_aggregate() {
    int w = (blockIdx.x * blockDim.x + threadIdx.x) >> 5;
    if (w >= NN) return;
    int lane = threadIdx.x & 31;
    float4 acc = { 0.f, 0.f, 0.f, 0.f };
    int p0 = g_rowptr[w], p1 = g_rowptr[w + 1];
    for (int p = p0; p < p1; p++) {
        int s = g_csrc[p];
        uint2 a = *(const uint2*)&g_xb[(size_t)s * 64 + lane * 2];
        acc.x += bf_lo(a.x); acc.y += bf_hi(a.x);
        acc.z += bf_lo(a.y); acc.w += bf_hi(a.y);
    }
    g_aggb[(size_t)w * 64 + lane * 2]     = pack_bf2(acc.x, acc.y);
    g_aggb[(size_t)w * 64 + lane * 2 + 1] = pack_bf2(acc.z, acc.w);
}

// ---------------- BatchNorm scalars (self-resetting) ----------------
__global__ void bn_final(const float* __restrict__ gamma, const float* __restrict__ beta) {
    int c = threadIdx.x;
    if (c >= HD) return;
    float su = g_bnsum[c], sq = g_bnsq[c];
    g_bnsum[c] = 0.f;
    g_bnsq[c]  = 0.f;
    float mu  = su / (float)NN;
    float var = sq / (float)NN - mu * mu;
    float sc  = gamma[c] * rsqrtf(var + EPSF);
    g_scale[c] = sc;
    g_shift[c] = beta[c] - mu * sc;
}

// ---------------- GAT ----------------
__global__ void gat_node1(const float* __restrict__ att_src, const float* __restrict__ att_dst) {
    int n = (blockIdx.x * blockDim.x + threadIdx.x) >> 5;
    if (n >= NN) return;
    int lane = threadIdx.x & 31;
    float s[4], d[4];
#pragma unroll
    for (int h = 0; h < 4; h++) {
        uint2 hp = *(const uint2*)&g_hfb[(size_t)n * 256 + h * 64 + lane * 2];
        float4 hv = { bf_lo(hp.x), bf_hi(hp.x), bf_lo(hp.y), bf_hi(hp.y) };
        float4 a1 = *(const float4*)&att_src[h * 128 + lane * 4];
        float4 a2 = *(const float4*)&att_dst[h * 128 + lane * 4];
        float ps = hv.x * a1.x + hv.y * a1.y + hv.z * a1.z + hv.w * a1.w;
        float pd = hv.x * a2.x + hv.y * a2.y + hv.z * a2.z + hv.w * a2.w;
#pragma unroll
        for (int off = 16; off > 0; off >>= 1) {
            ps += __shfl_xor_sync(0xffffffffu, ps, off);
            pd += __shfl_xor_sync(0xffffffffu, pd, off);
        }
        s[h] = ps; d[h] = pd;
    }
    if (lane == 0) {
#pragma unroll
        for (int h = 0; h < 4; h++) {
            g_as[n * 4 + h] = s[h];
            g_ad[n * 4 + h] = d[h];
        }
    }
}
__global__ void gat_node_all(const float* __restrict__ bg) {
    int n = (blockIdx.x * blockDim.x + threadIdx.x) >> 5;
    if (n >= NN) return;
    int lane = threadIdx.x & 31;
    float4 asn = *(const float4*)&g_as[n * 4];
    float4 adn = *(const float4*)&g_ad[n * 4];
    float sl0 = lrelu(asn.x + adn.x), sl1 = lrelu(asn.y + adn.y);
    float sl2 = lrelu(asn.z + adn.z), sl3 = lrelu(asn.w + adn.w);
    int p0 = g_rowptr[n], p1 = g_rowptr[n + 1];

    float m0 = sl0, m1 = sl1, m2 = sl2, m3 = sl3;
    for (int p = p0 + lane; p < p1; p += 32) {
        float4 a = *(const float4*)&g_as[g_csrc[p] * 4];
        m0 = fmaxf(m0, lrelu(a.x + adn.x)); m1 = fmaxf(m1, lrelu(a.y + adn.y));
        m2 = fmaxf(m2, lrelu(a.z + adn.z)); m3 = fmaxf(m3, lrelu(a.w + adn.w));
    }
#pragma unroll
    for (int o = 16; o > 0; o >>= 1) {
        m0 = fmaxf(m0, __shfl_xor_sync(~0u, m0, o));
        m1 = fmaxf(m1, __shfl_xor_sync(~0u, m1, o));
        m2 = fmaxf(m2, __shfl_xor_sync(~0u, m2, o));
        m3 = fmaxf(m3, __shfl_xor_sync(~0u, m3, o));
    }
    float d0 = 0.f, d1 = 0.f, d2 = 0.f, d3 = 0.f;
    for (int p = p0 + lane; p < p1; p += 32) {
        float4 a = *(const float4*)&g_as[g_csrc[p] * 4];
        d0 += __expf(lrelu(a.x + adn.x) - m0); d1 += __expf(lrelu(a.y + adn.y) - m1);
        d2 += __expf(lrelu(a.z + adn.z) - m2); d3 += __expf(lrelu(a.w + adn.w) - m3);
    }
#pragma unroll
    for (int o = 16; o > 0; o >>= 1) {
        d0 += __shfl_xor_sync(~0u, d0, o); d1 += __shfl_xor_sync(~0u, d1, o);
        d2 += __shfl_xor_sync(~0u, d2, o); d3 += __shfl_xor_sync(~0u, d3, o);
    }
    d0 += __expf(sl0 - m0); d1 += __expf(sl1 - m1);
    d2 += __expf(sl2 - m2); d3 += __expf(sl3 - m3);
    float i0 = 1.f / d0, i1 = 1.f / d1, i2 = 1.f / d2, i3 = 1.f / d3;

    float w0 = __expf(sl0 - m0) * i0, w1 = __expf(sl1 - m1) * i1;
    float w2 = __expf(sl2 - m2) * i2, w3 = __expf(sl3 - m3) * i3;
    size_t base = (size_t)n * 256 + lane * 2;
    uint2 hp0 = *(const uint2*)&g_hfb[base];
    uint2 hp1 = *(const uint2*)&g_hfb[base + 64];
    uint2 hp2 = *(const uint2*)&g_hfb[base + 128];
    uint2 hp3 = *(const uint2*)&g_hfb[base + 192];
    float4 A0 = { w0 * bf_lo(hp0.x), w0 * bf_hi(hp0.x), w0 * bf_lo(hp0.y), w0 * bf_hi(hp0.y) };
    float4 A1 = { w1 * bf_lo(hp1.x), w1 * bf_hi(hp1.x), w1 * bf_lo(hp1.y), w1 * bf_hi(hp1.y) };
    float4 A2 = { w2 * bf_lo(hp2.x), w2 * bf_hi(hp2.x), w2 * bf_lo(hp2.y), w2 * bf_hi(hp2.y) };
    float4 A3 = { w3 * bf_lo(hp3.x), w3 * bf_hi(hp3.x), w3 * bf_lo(hp3.y), w3 * bf_hi(hp3.y) };
    for (int p = p0; p < p1; p++) {
        int s = g_csrc[p];
        float4 a = *(const float4*)&g_as[s * 4];
        float e0 = __expf(lrelu(a.x + adn.x) - m0) * i0;
        float e1 = __expf(lrelu(a.y + adn.y) - m1) * i1;
        float e2 = __expf(lrelu(a.z + adn.z) - m2) * i2;
        float e3 = __expf(lrelu(a.w + adn.w) - m3) * i3;
        size_t sbx = (size_t)s * 256 + lane * 2;
        uint2 v0 = *(const uint2*)&g_hfb[sbx];
        uint2 v1 = *(const uint2*)&g_hfb[sbx + 64];
        uint2 v2 = *(const uint2*)&g_hfb[sbx + 128];
        uint2 v3 = *(const uint2*)&g_hfb[sbx + 192];
        A0.x += e0 * bf_lo(v0.x); A0.y += e0 * bf_hi(v0.x); A0.z += e0 * bf_lo(v0.y); A0.w += e0 * bf_hi(v0.y);
        A1.x += e1 * bf_lo(v1.x); A1.y += e1 * bf_hi(v1.x); A1.z += e1 * bf_lo(v1.y); A1.w += e1 * bf_hi(v1.y);
        A2.x += e2 * bf_lo(v2.x); A2.y += e2 * bf_hi(v2.x); A2.z += e2 * bf_lo(v2.y); A2.w += e2 * bf_hi(v2.y);
        A3.x += e3 * bf_lo(v3.x); A3.y += e3 * bf_hi(v3.x); A3.z += e3 * bf_lo(v3.y); A3.w += e3 * bf_hi(v3.y);
    }
    float4 bg4 = *(const float4*)&bg[lane * 4];
    float4 o4;
    o4.x = (A0.x + A1.x + A2.x + A3.x) * 0.25f + bg4.x;
    o4.y = (A0.y + A1.y + A2.y + A3.y) * 0.25f + bg4.y;
    o4.z = (A0.z + A1.z + A2.z + A3.z) * 0.25f + bg4.z;
    o4.w = (A0.w + A1.w + A2.w + A3.w) * 0.25f + bg4.w;
    *(float4*)&g_x[(size_t)n * HD + lane * 4] = o4;
}

// ---------------- pooling + fc ----------------
__device__ __forceinline__ int lbound(const int* a, int n, int key) {
    int lo = 0, hi = n;
    while (lo < hi) { int mid = (lo + hi) >> 1; if (a[mid] < key) lo = mid + 1; else hi = mid; }
    return lo;
}
__global__ void pool_kernel(const int* __restrict__ batch) {
    int g = blockIdx.x;
    int c = threadIdx.x;
    __shared__ int slo, shi;
    if (c == 0) { slo = lbound(batch, NN, g); shi = lbound(batch, NN, g + 1); }
    __syncthreads();
    int lo = slo, hi = shi;
    float a0 = 0.f, a1 = 0.f, a2 = 0.f, a3 = 0.f;
    int n = lo;
    for (; n + 4 <= hi; n += 4) {
        a0 += g_x[(size_t)n * HD + c];
        a1 += g_x[(size_t)(n + 1) * HD + c];
        a2 += g_x[(size_t)(n + 2) * HD + c];
        a3 += g_x[(size_t)(n + 3) * HD + c];
    }
    for (; n < hi; n++) a0 += g_x[(size_t)n * HD + c];
    float s = (a0 + a1) + (a2 + a3);
    g_pool[g * HD + c] = s / fmaxf((float)(hi - lo), 1.f);
}
__global__ void final_kernel(const float* __restrict__ Wfc, const float* __restrict__ bfc,
                             float* __restrict__ out) {
    int idx = blockIdx.x * blockDim.x + threadIdx.x;
    if (idx >= NG * NOUT) return;
    int g = idx / NOUT, o = idx % NOUT;
    float s = bfc[o];
#pragma unroll 8
    for (int k = 0; k < HD; k++) s += g_pool[g * HD + k] * Wfc[k * NOUT + o];
    out[idx] = s;
}

// ---------------- driver ----------------
extern "C" void kernel_launch(void* const* d_in, const int* in_sizes, int n_in,
                              void* d_out, int out_size) {
    const float* x_in      = (const float*)d_in[0];
    const float* edge_attr = (const float*)d_in[1];
    const int*   ei        = (const int*)d_in[2];
    const int*   batch     = (const int*)d_in[3];
    const float* Wn   = (const float*)d_in[4];
    const float* bn_b = (const float*)d_in[5];
    const float* We   = (const float*)d_in[6];
    const float* be_b = (const float*)d_in[7];
    const float* W1   = (const float*)d_in[8];
    const float* b1   = (const float*)d_in[9];
    const float* W2   = (const float*)d_in[10];
    const float* b2   = (const float*)d_in[11];
    const float* gamma= (const float*)d_in[12];
    const float* beta = (const float*)d_in[13];
    const float* Wg   = (const float*)d_in[14];
    const float* att_src = (const float*)d_in[15];
    const float* att_dst = (const float*)d_in[16];
    const float* bg   = (const float*)d_in[17];
    const float* Wfc  = (const float*)d_in[18];
    const float* bfc  = (const float*)d_in[19];
    float* out = (float*)d_out;

    cudaFuncSetAttribute(mma_gemm<true ,false,false,true ,true ,true >,
                         cudaFuncAttributeMaxDynamicSharedMemorySize, SM_TOT);
    cudaFuncSetAttribute(mma_gemm<false,false,true ,false,false,true >,
                         cudaFuncAttributeMaxDynamicSharedMemorySize, SM_TOT);
    cudaFuncSetAttribute(mma_gemm<false,true ,false,true ,false,false>,
                         cudaFuncAttributeMaxDynamicSharedMemorySize, SM_TOT);
    cudaFuncSetAttribute(comp_wnw1, cudaFuncAttributeMaxDynamicSharedMemorySize, 131072);
    cudaFuncSetAttribute(comp_v,    cudaFuncAttributeMaxDynamicSharedMemorySize, 83968);

    const int TB = 256;
    const int NODE_BLK = (NN + TB - 1) / TB;
    const int EDGE_BLK = (NE + TB - 1) / TB;
    const int WARP_BLK = (NN * 32 + TB - 1) / TB;
    const int VEC_BLK  = (NN * 64 + TB - 1) / TB;
    const dim3 GEMM_G(782, 1);
    const dim3 GEMM_G4(782, 4);

    // prologue
    prep_weights<<<14, 256>>>(W2, Wg);
    comp_wnw1<<<10, 256, 131072>>>(Wn, W1);
    comp_v<<<10, 256, 83968>>>(We, W1, bn_b, be_b);
    cvt_x<<<VEC_BLK, TB>>>(x_in);
    zero_deg<<<NODE_BLK, TB>>>();
    hist_kernel<<<EDGE_BLK, TB>>>(ei);
    scan_blocks<<<49, 1024>>>();
    scan_tops<<<1, 64>>>();
    scan_apply<<<NODE_BLK, TB>>>();
    scatter_kernel<<<EDGE_BLK, TB>>>(ei);
    eagg_kernel<<<WARP_BLK, TB>>>(edge_attr);
    we_gemm<<<dim3(391, 10), 256>>>();

    // ---- 10 GINE layers ----
    for (int l = 0; l < NL; l++) {
        if (l > 0) normrelu_bf16<<<VEC_BLK, TB>>>();
        gine_aggregate<<<WARP_BLK, TB>>>();
        mma_gemm<true ,false,false,true ,true ,true ><<<GEMM_G, 256, SM_TOT>>>(
            nullptr, U_AGGB, l, b1 + l * HD, U_TB, HD, l);
        mma_gemm<false,false,true ,false,false,true ><<<GEMM_G, 256, SM_TOT>>>(
            nullptr, U_TB, 20 + l, b2 + l * HD, 0, HD, 0);
        bn_final<<<1, 128>>>(gamma + l * HD, beta + l * HD);
    }

    // ---- GAT (A = g_o with layer-9 norm+relu applied in-load) ----
    mma_gemm<false,true ,false,true ,false,false><<<GEMM_G4, 256, SM_TOT>>>(
        nullptr, 0, 40, nullptr, U_HFB, 512, 0);
    gat_node1<<<WARP_BLK, TB>>>(att_src, att_dst);
    gat_node_all<<<WARP_BLK, TB>>>(bg);

    // ---- pool + fc ----
    pool_kernel<<<NG, 128>>>(batch);
    final_kernel<<<(NG * NOUT + TB - 1) / TB, TB>>>(Wfc, bfc, out);
}

// round 14
// speedup vs baseline: 1.3443x; 1.1270x over previous
#include <cuda_runtime.h>
#include <cuda_bf16.h>

// ---------------- problem constants ----------------
constexpr int NN   = 50000;
constexpr int NE   = 512000;
constexpr int HD   = 128;
constexpr int EDIM = 32;
constexpr int NL   = 10;
constexpr int NG   = 64;
constexpr int NOUT = 10;
constexpr float EPSF  = 1e-5f;
constexpr float SLOPE = 0.2f;

typedef unsigned long long u64;
typedef unsigned int u32;

// ---------------- generic helpers ----------------
__device__ __forceinline__ float lrelu(float v) { return v < 0.f ? SLOPE * v : v; }
__device__ __forceinline__ u32 smem_u32(const void* p) {
    u32 a; asm("{ .reg .u64 t; cvta.to.shared.u64 t, %1; cvt.u32.u64 %0, t; }" : "=r"(a) : "l"(p));
    return a;
}
__device__ __forceinline__ u32 pack_bf2(float a, float b) {
    return (u32)__bfloat16_as_ushort(__float2bfloat16(a)) |
           ((u32)__bfloat16_as_ushort(__float2bfloat16(b)) << 16);
}
__device__ __forceinline__ float bf_lo(u32 v) {
    return __bfloat162float(__ushort_as_bfloat16((unsigned short)(v & 0xffff)));
}
__device__ __forceinline__ float bf_hi(u32 v) {
    return __bfloat162float(__ushort_as_bfloat16((unsigned short)(v >> 16)));
}

// ---------------- mma.sync helpers ----------------
__device__ __forceinline__ void ldsm_x4(u32* r, u32 addr) {
    asm volatile("ldmatrix.sync.aligned.m8n8.x4.shared.b16 {%0,%1,%2,%3}, [%4];"
                 : "=r"(r[0]), "=r"(r[1]), "=r"(r[2]), "=r"(r[3]) : "r"(addr));
}
__device__ __forceinline__ void ldsm_x2t(u32* r, u32 addr) {
    asm volatile("ldmatrix.sync.aligned.m8n8.x2.trans.shared.b16 {%0,%1}, [%2];"
                 : "=r"(r[0]), "=r"(r[1]) : "r"(addr));
}
__device__ __forceinline__ void mma16816(float* c, const u32* a, const u32* b) {
    asm volatile("mma.sync.aligned.m16n8k16.row.col.f32.bf16.bf16.f32 "
                 "{%0,%1,%2,%3}, {%4,%5,%6,%7}, {%8,%9}, {%0,%1,%2,%3};"
                 : "+f"(c[0]), "+f"(c[1]), "+f"(c[2]), "+f"(c[3])
                 : "r"(a[0]), "r"(a[1]), "r"(a[2]), "r"(a[3]), "r"(b[0]), "r"(b[1]));
}
__device__ __forceinline__ void cp_async16(u32 dst, const void* src) {
    asm volatile("cp.async.cg.shared.global [%0], [%1], 16;" :: "r"(dst), "l"(src));
}
__device__ __forceinline__ void cp_async_wait_all() {
    asm volatile("cp.async.commit_group;");
    asm volatile("cp.async.wait_group 0;" ::: "memory");
}

// ---------------- device scratch ----------------
__device__ __align__(16) u32   g_xb[NN * 64];           // x packed bf16x2
__device__ __align__(16) u32   g_aggb[NN * 64];         // gathered sum, bf16x2
__device__ __align__(16) u32   g_hfb[NN * 256];         // GAT features bf16x2
__device__ __align__(16) u32   g_agg10b[(size_t)NL * NN * 64]; // E10 terms bf16x2
__device__ __align__(16) float g_o[NN * HD];
__device__ __align__(16) float g_x[NN * HD];
__device__ __align__(16) float g_eagg[NN * EDIM];
__device__           float g_u[NL * HD];
__device__           float g_degf[NN];
__device__           int   g_deg[NN];
__device__           int   g_rowptr[NN + 1];
__device__           int   g_cursor[NN];
__device__           int   g_csrc[NE];
__device__           int   g_ceid[NE];
__device__           int   g_bsum[64];
__device__           int   g_boff[64];
__device__ __align__(16) float g_as[NN * 4];
__device__ __align__(16) float g_ad[NN * 4];
__device__ __align__(16) float g_bnsum[HD];
__device__ __align__(16) float g_bnsq[HD];
__device__ __align__(16) float g_scale[HD];
__device__ __align__(16) float g_shift[HD];
__device__ __align__(16) float g_pool[NG * HD];

// Prepped weights: 0..9 WnW1[l], 20..29 W2[l], 30..39 V[l]=We@W1, 40..43 Wg blocks.
constexpr int NMAT = 44;
constexpr int WPAD = 136;
constexpr int WHALF = 128 * WPAD * 2;           // 34816
constexpr int WMAT_BYTES = 2 * WHALF;
__device__ __align__(16) char g_wb[(size_t)NMAT * WMAT_BYTES];

__device__ __forceinline__ void split_store(char* dst, int k, int n, float v) {
    __nv_bfloat16 h = __float2bfloat16(v);
    __nv_bfloat16 l = __float2bfloat16(v - __bfloat162float(h));
    ((__nv_bfloat16*)dst)[k * WPAD + n]           = h;
    ((__nv_bfloat16*)(dst + WHALF))[k * WPAD + n] = l;
}

// ---------------- weight prep ----------------
__global__ void prep_weights(const float* __restrict__ W2, const float* __restrict__ Wg) {
    int m = blockIdx.x;            // 0..13
    int slot = (m < 10) ? (20 + m) : (40 + (m - 10));
    char* dst = g_wb + (size_t)slot * WMAT_BYTES;
    for (int idx = threadIdx.x; idx < 16384; idx += blockDim.x) {
        int k = idx >> 7, n = idx & 127;
        float v = (m < 10) ? W2[(size_t)m * 16384 + k * 128 + n]
                           : Wg[(size_t)k * 512 + (m - 10) * 128 + n];
        split_store(dst, k, n, v);
    }
}
__global__ void comp_wnw1(const float* __restrict__ Wn, const float* __restrict__ W1) {
    extern __shared__ float s[];
    float* sA = s;
    float* sB = s + 16384;
    int l = blockIdx.x, tid = threadIdx.x;
    const float* A = Wn + (size_t)l * 16384;
    const float* B = W1 + (size_t)l * 16384;
    for (int i = tid; i < 16384; i += 256) { sA[i] = A[i]; sB[i] = B[i]; }
    __syncthreads();
    char* dst = g_wb + (size_t)l * WMAT_BYTES;
    int k = tid >> 1, c0 = (tid & 1) * 64;
    for (int n = c0; n < c0 + 64; n++) {
        float acc = 0.f;
#pragma unroll 8
        for (int m = 0; m < 128; m++) acc += sA[k * 128 + m] * sB[m * 128 + n];
        split_store(dst, k, n, acc);
    }
}
__global__ void comp_v(const float* __restrict__ We, const float* __restrict__ W1,
                       const float* __restrict__ bnb, const float* __restrict__ beb) {
    extern __shared__ float s[];
    float* sB  = s;
    float* sE  = s + 16384;
    float* sbb = s + 20480;
    int l = blockIdx.x, tid = threadIdx.x;
    const float* B = W1 + (size_t)l * 16384;
    const float* E = We + (size_t)l * 4096;
    for (int i = tid; i < 16384; i += 256) sB[i] = B[i];
    for (int i = tid; i < 4096; i += 256) sE[i] = E[i];
    if (tid < 128) sbb[tid] = bnb[l * 128 + tid] + beb[l * 128 + tid];
    __syncthreads();
    char* dst = g_wb + (size_t)(30 + l) * WMAT_BYTES;
    int k = tid >> 3, c0 = (tid & 7) * 16;
    for (int n = c0; n < c0 + 16; n++) {
        float acc = 0.f;
#pragma unroll 8
        for (int m = 0; m < 128; m++) acc += sE[k * 128 + m] * sB[m * 128 + n];
        split_store(dst, k, n, acc);
    }
    if (tid < 128) {
        float acc = 0.f;
#pragma unroll 8
        for (int m = 0; m < 128; m++) acc += sbb[m] * sB[m * 128 + tid];
        g_u[l * 128 + tid] = acc;
    }
}

// ---------------- SMEM layout for fused/GAT GEMMs ----------------
constexpr int AHALF = 64 * WPAD * 2;   // 17408 (single A buffer)
constexpr int SM_A  = 0;
constexpr int SM_BH = AHALF;           // 17408
constexpr int SM_BL = AHALF + WHALF;   // 52224
constexpr int SM_TOT = AHALF + 2 * WHALF;   // 87040 -> 2 CTAs/SM

// shared mainloop: 2 passes (Bh, Bl) over bf16 A at SM_A
__device__ __forceinline__ void run_mainloop(u32 sb, int wm, int wn, int lane,
                                             float acc[2][4][4]) {
#pragma unroll
    for (int i = 0; i < 2; i++)
#pragma unroll
        for (int j = 0; j < 4; j++)
#pragma unroll
            for (int q = 0; q < 4; q++) acc[i][j][q] = 0.f;
    const u32 boff[2] = { SM_BH, SM_BL };
#pragma unroll
    for (int p = 0; p < 2; p++) {
        u32 sa0 = sb + SM_A + ((wm * 32 + (lane & 15)) * WPAD + (lane >> 4) * 8) * 2;
        u32 sb0 = sb + boff[p] + ((lane & 15) * WPAD + wn * 32) * 2;
#pragma unroll
        for (int k = 0; k < 8; k++) {
            u32 af[2][4];
#pragma unroll
            for (int i = 0; i < 2; i++)
                ldsm_x4(af[i], sa0 + i * 16 * (WPAD * 2) + k * 32);
            u32 bf[4][2];
#pragma unroll
            for (int j = 0; j < 4; j++)
                ldsm_x2t(bf[j], sb0 + k * 16 * (WPAD * 2) + j * 16);
#pragma unroll
            for (int i = 0; i < 2; i++)
#pragma unroll
                for (int j = 0; j < 4; j++)
                    mma16816(acc[i][j], af[i], bf[j]);
        }
    }
}

// ---------------- fused layer: t=relu(aggb@WnW1 + E10 + b1); o = t@W2 + b2 (+BN stats) ----------------
__global__ void __launch_bounds__(256, 2)
fused_layer(int l, const float* __restrict__ b1, const float* __restrict__ b2)
{
    extern __shared__ __align__(16) char smem[];
    u32 sb = smem_u32(smem);
    int tid = threadIdx.x, wid = tid >> 5, lane = tid & 31;
    int row0 = blockIdx.x * 64;
    int wm = wid >> 2, wn = wid & 3;

    // B <- WnW1[l] (hi+lo) async
    {
        const char* src = g_wb + (size_t)l * WMAT_BYTES + tid * 16;
        u32 dst = sb + SM_BH + tid * 16;
#pragma unroll
        for (int i = 0; i < 17; i++)
            cp_async16(dst + i * 4096, src + i * 4096);
    }
    // A <- aggb (bf16 raw copy)
    {
        int r = tid >> 2, cb = (tid & 3) * 32;
        bool valid = (row0 + r) < NN;
        u32* AS = (u32*)(smem + SM_A) + ((r * WPAD + cb) >> 1);
        const u32* arow = g_aggb + (size_t)(row0 + r) * 64 + (cb >> 1);
#pragma unroll
        for (int i = 0; i < 16; i++)
            AS[i] = valid ? arow[i] : 0u;
    }
    cp_async_wait_all();
    __syncthreads();

    float acc[2][4][4];
    run_mainloop(sb, wm, wn, lane, acc);
    __syncthreads();                       // everyone done with A and B

    // start W2 load while we write t into the A buffer
    {
        const char* src = g_wb + (size_t)(20 + l) * WMAT_BYTES + tid * 16;
        u32 dst = sb + SM_BH + tid * 16;
#pragma unroll
        for (int i = 0; i < 17; i++)
            cp_async16(dst + i * 4096, src + i * 4096);
    }
    // epilogue1: t = relu(acc + b1 + E10) -> SMEM A (bf16)
    {
        const u32* E = g_agg10b + (size_t)l * NN * 64;
#pragma unroll
        for (int i = 0; i < 2; i++) {
            int rl0 = wm * 32 + i * 16 + (lane >> 2);
#pragma unroll
            for (int half = 0; half < 2; half++) {
                int rloc = rl0 + half * 8;
                int row = row0 + rloc;
                bool valid = row < NN;
#pragma unroll
                for (int j = 0; j < 4; j++) {
                    int cc = wn * 32 + j * 8 + (lane & 3) * 2;
                    float v0 = 0.f, v1 = 0.f;
                    if (valid) {
                        u32 e = E[(size_t)row * 64 + (cc >> 1)];
                        v0 = fmaxf(acc[i][j][half * 2 + 0] + b1[cc]     + bf_lo(e), 0.f);
                        v1 = fmaxf(acc[i][j][half * 2 + 1] + b1[cc + 1] + bf_hi(e), 0.f);
                    }
                    *(u32*)(smem + SM_A + (rloc * WPAD + cc) * 2) = pack_bf2(v0, v1);
                }
            }
        }
    }
    cp_async_wait_all();
    __syncthreads();

    run_mainloop(sb, wm, wn, lane, acc);

    // epilogue2: o = acc + b2 -> fp32 g_o, accumulate BN stats
    float csum[8], csq[8];
#pragma unroll
    for (int q = 0; q < 8; q++) { csum[q] = 0.f; csq[q] = 0.f; }
#pragma unroll
    for (int i = 0; i < 2; i++) {
        int ra = row0 + wm * 32 + i * 16 + (lane >> 2);
#pragma unroll
        for (int half = 0; half < 2; half++) {
            int row = ra + half * 8;
            if (row < NN) {
#pragma unroll
                for (int j = 0; j < 4; j++) {
                    int cc = wn * 32 + j * 8 + (lane & 3) * 2;
                    float v0 = acc[i][j][half * 2 + 0] + b2[cc];
                    float v1 = acc[i][j][half * 2 + 1] + b2[cc + 1];
                    csum[j * 2]     += v0; csq[j * 2]     += v0 * v0;
                    csum[j * 2 + 1] += v1; csq[j * 2 + 1] += v1 * v1;
                    *(float2*)&g_o[(size_t)row * HD + cc] = make_float2(v0, v1);
                }
            }
        }
    }
    {
        float* ssum = (float*)smem;
        float* ssq  = ssum + 128;
        __syncthreads();
        if (tid < 128) { ssum[tid] = 0.f; ssq[tid] = 0.f; }
        __syncthreads();
#pragma unroll
        for (int j = 0; j < 4; j++) {
#pragma unroll
            for (int c = 0; c < 2; c++) {
                int col = wn * 32 + j * 8 + (lane & 3) * 2 + c;
                atomicAdd(&ssum[col], csum[j * 2 + c]);
                atomicAdd(&ssq[col],  csq[j * 2 + c]);
            }
        }
        __syncthreads();
        if (tid < 128) {
            atomicAdd(&g_bnsum[tid], ssum[tid]);
            atomicAdd(&g_bnsq[tid],  ssq[tid]);
        }
    }
}

// ---------------- GAT GEMM: hfeat = normrelu(o) @ Wg -> bf16 ----------------
__global__ void __launch_bounds__(256, 2)
gat_gemm()
{
    extern __shared__ __align__(16) char smem[];
    u32 sb = smem_u32(smem);
    int tid = threadIdx.x, wid = tid >> 5, lane = tid & 31;
    int row0 = blockIdx.x * 64;
    int colb = blockIdx.y * 128;
    int wm = wid >> 2, wn = wid & 3;

    {
        const char* src = g_wb + (size_t)(40 + blockIdx.y) * WMAT_BYTES + tid * 16;
        u32 dst = sb + SM_BH + tid * 16;
#pragma unroll
        for (int i = 0; i < 17; i++)
            cp_async16(dst + i * 4096, src + i * 4096);
    }
    {
        int r = tid >> 2, cb = (tid & 3) * 32;
        bool valid = (row0 + r) < NN;
        u32* AS = (u32*)(smem + SM_A) + ((r * WPAD + cb) >> 1);
        const float2* arow = (const float2*)(g_o + (size_t)(row0 + r) * 128 + cb);
#pragma unroll 8
        for (int i = 0; i < 16; i++) {
            float2 v = valid ? arow[i] : make_float2(0.f, 0.f);
            float2 sc = *(const float2*)&g_scale[cb + 2 * i];
            float2 sh = *(const float2*)&g_shift[cb + 2 * i];
            v.x = fmaxf(v.x * sc.x + sh.x, 0.f);
            v.y = fmaxf(v.y * sc.y + sh.y, 0.f);
            AS[i] = pack_bf2(v.x, v.y);
        }
    }
    cp_async_wait_all();
    __syncthreads();

    float acc[2][4][4];
    run_mainloop(sb, wm, wn, lane, acc);

#pragma unroll
    for (int i = 0; i < 2; i++) {
        int ra = row0 + wm * 32 + i * 16 + (lane >> 2);
#pragma unroll
        for (int half = 0; half < 2; half++) {
            int row = ra + half * 8;
            if (row < NN) {
#pragma unroll
                for (int j = 0; j < 4; j++) {
                    int cc = wn * 32 + j * 8 + (lane & 3) * 2;
                    float v0 = acc[i][j][half * 2 + 0];
                    float v1 = acc[i][j][half * 2 + 1];
                    g_hfb[(size_t)row * 256 + ((colb + cc) >> 1)] = pack_bf2(v0, v1);
                }
            }
        }
    }
}

// ---------------- batched E10 GEMM (2-pass): g_agg10b[l] = Eagg @ V[l] + deg*u[l] ----------------
constexpr int EPAD = 40;
constexpr int WE_A  = 0;
constexpr int WE_BH = 10240;
constexpr int WE_BL = 18944;
constexpr int WE_TOT = 27648;

__global__ void __launch_bounds__(256)
we_gemm()
{
    __shared__ __align__(16) char smem[WE_TOT];
    u32 sb = smem_u32(smem);
    int tid = threadIdx.x, wid = tid >> 5, lane = tid & 31;
    int row0 = blockIdx.x * 128;
    int l = blockIdx.y;

    {
        const char* mat = g_wb + (size_t)(30 + l) * WMAT_BYTES;
        for (int i = tid; i < 544; i += 256) {
            cp_async16(sb + WE_BH + i * 16, mat + i * 16);
            cp_async16(sb + WE_BL + i * 16, mat + WHALF + i * 16);
        }
    }
    {
        int r = tid >> 1, cb = (tid & 1) * 16;
        bool valid = (row0 + r) < NN;
        const float2* arow = (const float2*)(g_eagg + (size_t)(row0 + r) * 32 + cb);
        u32* AS = (u32*)(smem + WE_A) + ((r * EPAD + cb) >> 1);
#pragma unroll
        for (int i = 0; i < 8; i++) {
            float2 v = valid ? arow[i] : make_float2(0.f, 0.f);
            AS[i] = pack_bf2(v.x, v.y);
        }
    }
    cp_async_wait_all();
    __syncthreads();

    int wm = wid >> 2, wn = wid & 3;
    float acc[4][4][4];
#pragma unroll
    for (int i = 0; i < 4; i++)
#pragma unroll
        for (int j = 0; j < 4; j++)
#pragma unroll
            for (int q = 0; q < 4; q++) acc[i][j][q] = 0.f;

    const u32 boff[2] = { WE_BH, WE_BL };
#pragma unroll
    for (int p = 0; p < 2; p++) {
        u32 sa0 = sb + WE_A + ((wm * 64 + (lane & 15)) * EPAD + (lane >> 4) * 8) * 2;
        u32 sb0 = sb + boff[p] + ((lane & 15) * WPAD + wn * 32) * 2;
#pragma unroll
        for (int k = 0; k < 2; k++) {
            u32 af[4][4];
#pragma unroll
            for (int i = 0; i < 4; i++)
                ldsm_x4(af[i], sa0 + i * 16 * (EPAD * 2) + k * 32);
            u32 bf[4][2];
#pragma unroll
            for (int j = 0; j < 4; j++)
                ldsm_x2t(bf[j], sb0 + k * 16 * (WPAD * 2) + j * 16);
#pragma unroll
            for (int i = 0; i < 4; i++)
#pragma unroll
                for (int j = 0; j < 4; j++)
                    mma16816(acc[i][j], af[i], bf[j]);
        }
    }

    u32* C = g_agg10b + (size_t)l * NN * 64;
    const float* bias = g_u + l * HD;
#pragma unroll
    for (int i = 0; i < 4; i++) {
        int ra = row0 + wm * 64 + i * 16 + (lane >> 2);
#pragma unroll
        for (int half = 0; half < 2; half++) {
            int row = ra + half * 8;
            if (row < NN) {
                float rs = g_degf[row];
#pragma unroll
                for (int j = 0; j < 4; j++) {
                    int cc = wn * 32 + j * 8 + (lane & 3) * 2;
                    float v0 = acc[i][j][half * 2 + 0] + rs * bias[cc];
                    float v1 = acc[i][j][half * 2 + 1] + rs * bias[cc + 1];
                    C[(size_t)row * 64 + (cc >> 1)] = pack_bf2(v0, v1);
                }
            }
        }
    }
}

// ---------------- CSR build ----------------
__global__ void zero_deg() {
    int i = blockIdx.x * blockDim.x + threadIdx.x;
    if (i < NN) g_deg[i] = 0;
    if (i < HD) { g_bnsum[i] = 0.f; g_bnsq[i] = 0.f; }
}
__global__ void hist_kernel(const int* __restrict__ ei) {
    int e = blockIdx.x * blockDim.x + threadIdx.x;
    if (e < NE) atomicAdd(&g_deg[ei[NE + e]], 1);
}
__global__ void scan_blocks() {
    __shared__ int wsum[32];
    int tid = threadIdx.x, lane = tid & 31, w = tid >> 5;
    int i = blockIdx.x * 1024 + tid;
    int v = (i < NN) ? g_deg[i] : 0;
    int x = v;
#pragma unroll
    for (int o = 1; o < 32; o <<= 1) { int t = __shfl_up_sync(~0u, x, o); if (lane >= o) x += t; }
    if (lane == 31) wsum[w] = x;
    __syncthreads();
    if (w == 0) {
        int s = wsum[lane];
#pragma unroll
        for (int o = 1; o < 32; o <<= 1) { int t = __shfl_up_sync(~0u, s, o); if (lane >= o) s += t; }
        wsum[lane] = s;
    }
    __syncthreads();
    int wexcl = (w == 0) ? 0 : wsum[w - 1];
    if (i < NN) g_rowptr[i] = wexcl + x - v;
    if (tid == 1023) g_bsum[blockIdx.x] = wsum[31];
}
__global__ void scan_tops() {
    int tid = threadIdx.x;
    __shared__ int sh[64];
    __shared__ int w0tot;
    int v = (tid < 49) ? g_bsum[tid] : 0;
    int lane = tid & 31, w = tid >> 5;
    int x = v;
#pragma unroll
    for (int o = 1; o < 32; o <<= 1) { int t = __shfl_up_sync(~0u, x, o); if (lane >= o) x += t; }
    if (w == 0 && lane == 31) w0tot = x;
    __syncthreads();
    int incl = x + (w == 1 ? w0tot : 0);
    sh[tid] = incl - v;
    __syncthreads();
    if (tid < 49) g_boff[tid] = sh[tid];
}
__global__ void scan_apply() {
    int i = blockIdx.x * blockDim.x + threadIdx.x;
    if (i >= NN) return;
    int rp = g_rowptr[i] + g_boff[i >> 10];
    g_rowptr[i] = rp;
    g_cursor[i] = rp;
    g_degf[i]   = (float)g_deg[i];
    if (i == 0) g_rowptr[NN] = NE;
}
__global__ void scatter_kernel(const int* __restrict__ ei) {
    int e = blockIdx.x * blockDim.x + threadIdx.x;
    if (e >= NE) return;
    int s = ei[e], d = ei[NE + e];
    int p = atomicAdd(&g_cursor[d], 1);
    g_csrc[p] = s;
    g_ceid[p] = e;
}
__global__ void eagg_kernel(const float* __restrict__ edge_attr) {
    int w = (blockIdx.x * blockDim.x + threadIdx.x) >> 5;
    if (w >= NN) return;
    int lane = threadIdx.x & 31;
    float acc = 0.f;
    int p0 = g_rowptr[w], p1 = g_rowptr[w + 1];
    for (int p = p0; p < p1; p++) {
        int e = g_ceid[p];
        acc += edge_attr[e * EDIM + lane];
    }
    g_eagg[w * EDIM + lane] = acc;
}

// ---------------- conversions ----------------
__global__ void cvt_x(const float* __restrict__ x) {
    int i = blockIdx.x * blockDim.x + threadIdx.x;
    if (i >= NN * 64) return;
    float2 v = ((const float2*)x)[i];
    g_xb[i] = pack_bf2(v.x, v.y);
}
__global__ void normrelu_bf16() {
    int i = blockIdx.x * blockDim.x + threadIdx.x;
    if (i >= NN * 64) return;
    float2 v = ((const float2*)g_o)[i];
    int c = i & 63;
    float2 sc = ((const float2*)g_scale)[c];
    float2 sh = ((const float2*)g_shift)[c];
    float a = fmaxf(v.x * sc.x + sh.x, 0.f);
    float b = fmaxf(v.y * sc.y + sh.y, 0.f);
    g_xb[i] = pack_bf2(a, b);
}

// ---------------- gather: aggb[n] = sum x_bf16[src] (bf16 out) ----------------
__global__ void gine_aggregate() {
    int w = (blockIdx.x * blockDim.x + threadIdx.x) >> 5;
    if (w >= NN) return;
    int lane = threadIdx.x & 31;
    float4 acc = { 0.f, 0.f, 0.f, 0.f };
    int p0 = g_rowptr[w], p1 = g_rowptr[w + 1];
    for (int p = p0; p < p1; p++) {
        int s = g_csrc[p];
        uint2 a = *(const uint2*)&g_xb[(size_t)s * 64 + lane * 2];
        acc.x += bf_lo(a.x); acc.y += bf_hi(a.x);
        acc.z += bf_lo(a.y); acc.w += bf_hi(a.y);
    }
    g_aggb[(size_t)w * 64 + lane * 2]     = pack_bf2(acc.x, acc.y);
    g_aggb[(size_t)w * 64 + lane * 2 + 1] = pack_bf2(acc.z, acc.w);
}

// ---------------- BatchNorm scalars (self-resetting) ----------------
__global__ void bn_final(const float* __restrict__ gamma, const float* __restrict__ beta) {
    int c = threadIdx.x;
    if (c >= HD) return;
    float su = g_bnsum[c], sq = g_bnsq[c];
    g_bnsum[c] = 0.f;
    g_bnsq[c]  = 0.f;
    float mu  = su / (float)NN;
    float var = sq / (float)NN - mu * mu;
    float sc  = gamma[c] * rsqrtf(var + EPSF);
    g_scale[c] = sc;
    g_shift[c] = beta[c] - mu * sc;
}

// ---------------- GAT ----------------
__global__ void gat_node1(const float* __restrict__ att_src, const float* __restrict__ att_dst) {
    int n = (blockIdx.x * blockDim.x + threadIdx.x) >> 5;
    if (n >= NN) return;
    int lane = threadIdx.x & 31;
    float s[4], d[4];
#pragma unroll
    for (int h = 0; h < 4; h++) {
        uint2 hp = *(const uint2*)&g_hfb[(size_t)n * 256 + h * 64 + lane * 2];
        float4 hv = { bf_lo(hp.x), bf_hi(hp.x), bf_lo(hp.y), bf_hi(hp.y) };
        float4 a1 = *(const float4*)&att_src[h * 128 + lane * 4];
        float4 a2 = *(const float4*)&att_dst[h * 128 + lane * 4];
        float ps = hv.x * a1.x + hv.y * a1.y + hv.z * a1.z + hv.w * a1.w;
        float pd = hv.x * a2.x + hv.y * a2.y + hv.z * a2.z + hv.w * a2.w;
#pragma unroll
        for (int off = 16; off > 0; off >>= 1) {
            ps += __shfl_xor_sync(0xffffffffu, ps, off);
            pd += __shfl_xor_sync(0xffffffffu, pd, off);
        }
        s[h] = ps; d[h] = pd;
    }
    if (lane == 0) {
#pragma unroll
        for (int h = 0; h < 4; h++) {
            g_as[n * 4 + h] = s[h];
            g_ad[n * 4 + h] = d[h];
        }
    }
}
__global__ void gat_node_all(const float* __restrict__ bg) {
    int n = (blockIdx.x * blockDim.x + threadIdx.x) >> 5;
    if (n >= NN) return;
    int lane = threadIdx.x & 31;
    float4 asn = *(const float4*)&g_as[n * 4];
    float4 adn = *(const float4*)&g_ad[n * 4];
    float sl0 = lrelu(asn.x + adn.x), sl1 = lrelu(asn.y + adn.y);
    float sl2 = lrelu(asn.z + adn.z), sl3 = lrelu(asn.w + adn.w);
    int p0 = g_rowptr[n], p1 = g_rowptr[n + 1];

    float m0 = sl0, m1 = sl1, m2 = sl2, m3 = sl3;
    for (int p = p0 + lane; p < p1; p += 32) {
        float4 a = *(const float4*)&g_as[g_csrc[p] * 4];
        m0 = fmaxf(m0, lrelu(a.x + adn.x)); m1 = fmaxf(m1, lrelu(a.y + adn.y));
        m2 = fmaxf(m2, lrelu(a.z + adn.z)); m3 = fmaxf(m3, lrelu(a.w + adn.w));
    }
#pragma unroll
    for (int o = 16; o > 0; o >>= 1) {
        m0 = fmaxf(m0, __shfl_xor_sync(~0u, m0, o));
        m1 = fmaxf(m1, __shfl_xor_sync(~0u, m1, o));
        m2 = fmaxf(m2, __shfl_xor_sync(~0u, m2, o));
        m3 = fmaxf(m3, __shfl_xor_sync(~0u, m3, o));
    }
    float d0 = 0.f, d1 = 0.f, d2 = 0.f, d3 = 0.f;
    for (int p = p0 + lane; p < p1; p += 32) {
        float4 a = *(const float4*)&g_as[g_csrc[p] * 4];
        d0 += __expf(lrelu(a.x + adn.x) - m0); d1 += __expf(lrelu(a.y + adn.y) - m1);
        d2 += __expf(lrelu(a.z + adn.z) - m2); d3 += __expf(lrelu(a.w + adn.w) - m3);
    }
#pragma unroll
    for (int o = 16; o > 0; o >>= 1) {
        d0 += __shfl_xor_sync(~0u, d0, o); d1 += __shfl_xor_sync(~0u, d1, o);
        d2 += __shfl_xor_sync(~0u, d2, o); d3 += __shfl_xor_sync(~0u, d3, o);
    }
    d0 += __expf(sl0 - m0); d1 += __expf(sl1 - m1);
    d2 += __expf(sl2 - m2); d3 += __expf(sl3 - m3);
    float i0 = 1.f / d0, i1 = 1.f / d1, i2 = 1.f / d2, i3 = 1.f / d3;

    float w0 = __expf(sl0 - m0) * i0, w1 = __expf(sl1 - m1) * i1;
    float w2 = __expf(sl2 - m2) * i2, w3 = __expf(sl3 - m3) * i3;
    size_t base = (size_t)n * 256 + lane * 2;
    uint2 hp0 = *(const uint2*)&g_hfb[base];
    uint2 hp1 = *(const uint2*)&g_hfb[base + 64];
    uint2 hp2 = *(const uint2*)&g_hfb[base + 128];
    uint2 hp3 = *(const uint2*)&g_hfb[base + 192];
    float4 A0 = { w0 * bf_lo(hp0.x), w0 * bf_hi(hp0.x), w0 * bf_lo(hp0.y), w0 * bf_hi(hp0.y) };
    float4 A1 = { w1 * bf_lo(hp1.x), w1 * bf_hi(hp1.x), w1 * bf_lo(hp1.y), w1 * bf_hi(hp1.y) };
    float4 A2 = { w2 * bf_lo(hp2.x), w2 * bf_hi(hp2.x), w2 * bf_lo(hp2.y), w2 * bf_hi(hp2.y) };
    float4 A3 = { w3 * bf_lo(hp3.x), w3 * bf_hi(hp3.x), w3 * bf_lo(hp3.y), w3 * bf_hi(hp3.y) };
    for (int p = p0; p < p1; p++) {
        int s = g_csrc[p];
        float4 a = *(const float4*)&g_as[s * 4];
        float e0 = __expf(lrelu(a.x + adn.x) - m0) * i0;
        float e1 = __expf(lrelu(a.y + adn.y) - m1) * i1;
        float e2 = __expf(lrelu(a.z + adn.z) - m2) * i2;
        float e3 = __expf(lrelu(a.w + adn.w) - m3) * i3;
        size_t sbx = (size_t)s * 256 + lane * 2;
        uint2 v0 = *(const uint2*)&g_hfb[sbx];
        uint2 v1 = *(const uint2*)&g_hfb[sbx + 64];
        uint2 v2 = *(const uint2*)&g_hfb[sbx + 128];
        uint2 v3 = *(const uint2*)&g_hfb[sbx + 192];
        A0.x += e0 * bf_lo(v0.x); A0.y += e0 * bf_hi(v0.x); A0.z += e0 * bf_lo(v0.y); A0.w += e0 * bf_hi(v0.y);
        A1.x += e1 * bf_lo(v1.x); A1.y += e1 * bf_hi(v1.x); A1.z += e1 * bf_lo(v1.y); A1.w += e1 * bf_hi(v1.y);
        A2.x += e2 * bf_lo(v2.x); A2.y += e2 * bf_hi(v2.x); A2.z += e2 * bf_lo(v2.y); A2.w += e2 * bf_hi(v2.y);
        A3.x += e3 * bf_lo(v3.x); A3.y += e3 * bf_hi(v3.x); A3.z += e3 * bf_lo(v3.y); A3.w += e3 * bf_hi(v3.y);
    }
    float4 bg4 = *(const float4*)&bg[lane * 4];
    float4 o4;
    o4.x = (A0.x + A1.x + A2.x + A3.x) * 0.25f + bg4.x;
    o4.y = (A0.y + A1.y + A2.y + A3.y) * 0.25f + bg4.y;
    o4.z = (A0.z + A1.z + A2.z + A3.z) * 0.25f + bg4.z;
    o4.w = (A0.w + A1.w + A2.w + A3.w) * 0.25f + bg4.w;
    *(float4*)&g_x[(size_t)n * HD + lane * 4] = o4;
}

// ---------------- pooling + fc ----------------
__device__ __forceinline__ int lbound(const int* a, int n, int key) {
    int lo = 0, hi = n;
    while (lo < hi) { int mid = (lo + hi) >> 1; if (a[mid] < key) lo = mid + 1; else hi = mid; }
    return lo;
}
__global__ void pool_kernel(const int* __restrict__ batch) {
    int g = blockIdx.x;
    int c = threadIdx.x;
    __shared__ int slo, shi;
    if (c == 0) { slo = lbound(batch, NN, g); shi = lbound(batch, NN, g + 1); }
    __syncthreads();
    int lo = slo, hi = shi;
    float a0 = 0.f, a1 = 0.f, a2 = 0.f, a3 = 0.f;
    int n = lo;
    for (; n + 4 <= hi; n += 4) {
        a0 += g_x[(size_t)n * HD + c];
        a1 += g_x[(size_t)(n + 1) * HD + c];
        a2 += g_x[(size_t)(n + 2) * HD + c];
        a3 += g_x[(size_t)(n + 3) * HD + c];
    }
    for (; n < hi; n++) a0 += g_x[(size_t)n * HD + c];
    float s = (a0 + a1) + (a2 + a3);
    g_pool[g * HD + c] = s / fmaxf((float)(hi - lo), 1.f);
}
__global__ void final_kernel(const float* __restrict__ Wfc, const float* __restrict__ bfc,
                             float* __restrict__ out) {
    int idx = blockIdx.x * blockDim.x + threadIdx.x;
    if (idx >= NG * NOUT) return;
    int g = idx / NOUT, o = idx % NOUT;
    float s = bfc[o];
#pragma unroll 8
    for (int k = 0; k < HD; k++) s += g_pool[g * HD + k] * Wfc[k * NOUT + o];
    out[idx] = s;
}

// ---------------- driver ----------------
extern "C" void kernel_launch(void* const* d_in, const int* in_sizes, int n_in,
                              void* d_out, int out_size) {
    const float* x_in      = (const float*)d_in[0];
    const float* edge_attr = (const float*)d_in[1];
    const int*   ei        = (const int*)d_in[2];
    const int*   batch     = (const int*)d_in[3];
    const float* Wn   = (const float*)d_in[4];
    const float* bn_b = (const float*)d_in[5];
    const float* We   = (const float*)d_in[6];
    const float* be_b = (const float*)d_in[7];
    const float* W1   = (const float*)d_in[8];
    const float* b1   = (const float*)d_in[9];
    const float* W2   = (const float*)d_in[10];
    const float* b2   = (const float*)d_in[11];
    const float* gamma= (const float*)d_in[12];
    const float* beta = (const float*)d_in[13];
    const float* Wg   = (const float*)d_in[14];
    const float* att_src = (const float*)d_in[15];
    const float* att_dst = (const float*)d_in[16];
    const float* bg   = (const float*)d_in[17];
    const float* Wfc  = (const float*)d_in[18];
    const float* bfc  = (const float*)d_in[19];
    float* out = (float*)d_out;

    cudaFuncSetAttribute(fused_layer, cudaFuncAttributeMaxDynamicSharedMemorySize, SM_TOT);
    cudaFuncSetAttribute(gat_gemm,    cudaFuncAttributeMaxDynamicSharedMemorySize, SM_TOT);
    cudaFuncSetAttribute(comp_wnw1, cudaFuncAttributeMaxDynamicSharedMemorySize, 131072);
    cudaFuncSetAttribute(comp_v,    cudaFuncAttributeMaxDynamicSharedMemorySize, 83968);

    const int TB = 256;
    const int NODE_BLK = (NN + TB - 1) / TB;
    const int EDGE_BLK = (NE + TB - 1) / TB;
    const int WARP_BLK = (NN * 32 + TB - 1) / TB;
    const int VEC_BLK  = (NN * 64 + TB - 1) / TB;
    const dim3 GEMM_G(782, 1);
    const dim3 GEMM_G4(782, 4);

    // prologue
    prep_weights<<<14, 256>>>(W2, Wg);
    comp_wnw1<<<10, 256, 131072>>>(Wn, W1);
    comp_v<<<10, 256, 83968>>>(We, W1, bn_b, be_b);
    cvt_x<<<VEC_BLK, TB>>>(x_in);
    zero_deg<<<NODE_BLK, TB>>>();
    hist_kernel<<<EDGE_BLK, TB>>>(ei);
    scan_blocks<<<49, 1024>>>();
    scan_tops<<<1, 64>>>();
    scan_apply<<<NODE_BLK, TB>>>();
    scatter_kernel<<<EDGE_BLK, TB>>>(ei);
    eagg_kernel<<<WARP_BLK, TB>>>(edge_attr);
    we_gemm<<<dim3(391, 10), 256>>>();

    // ---- 10 GINE layers (one fused GEMM kernel each) ----
    for (int l = 0; l < NL; l++) {
        if (l > 0) normrelu_bf16<<<VEC_BLK, TB>>>();
        gine_aggregate<<<WARP_BLK, TB>>>();
        fused_layer<<<GEMM_G, 256, SM_TOT>>>(l, b1 + l * HD, b2 + l * HD);
        bn_final<<<1, 128>>>(gamma + l * HD, beta + l * HD);
    }

    // ---- GAT (A = g_o with layer-9 norm+relu applied in-load) ----
    gat_gemm<<<GEMM_G4, 256, SM_TOT>>>();
    gat_node1<<<WARP_BLK, TB>>>(att_src, att_dst);
    gat_node_all<<<WARP_BLK, TB>>>(bg);

    // ---- pool + fc ----
    pool_kernel<<<NG, 128>>>(batch);
    final_kernel<<<(NG * NOUT + TB - 1) / TB, TB>>>(Wfc, bfc, out);
}

// round 15
// speedup vs baseline: 1.3697x; 1.0189x over previous
#include <cuda_runtime.h>
#include <cuda_bf16.h>

// ---------------- problem constants ----------------
constexpr int NN   = 50000;
constexpr int NE   = 512000;
constexpr int HD   = 128;
constexpr int EDIM = 32;
constexpr int NL   = 10;
constexpr int NG   = 64;
constexpr int NOUT = 10;
constexpr float EPSF  = 1e-5f;
constexpr float SLOPE = 0.2f;

typedef unsigned long long u64;
typedef unsigned int u32;

// ---------------- generic helpers ----------------
__device__ __forceinline__ float lrelu(float v) { return v < 0.f ? SLOPE * v : v; }
__device__ __forceinline__ u32 smem_u32(const void* p) {
    u32 a; asm("{ .reg .u64 t; cvta.to.shared.u64 t, %1; cvt.u32.u64 %0, t; }" : "=r"(a) : "l"(p));
    return a;
}
__device__ __forceinline__ u32 pack_bf2(float a, float b) {
    return (u32)__bfloat16_as_ushort(__float2bfloat16(a)) |
           ((u32)__bfloat16_as_ushort(__float2bfloat16(b)) << 16);
}
__device__ __forceinline__ float bf_lo(u32 v) {
    return __bfloat162float(__ushort_as_bfloat16((unsigned short)(v & 0xffff)));
}
__device__ __forceinline__ float bf_hi(u32 v) {
    return __bfloat162float(__ushort_as_bfloat16((unsigned short)(v >> 16)));
}

// ---------------- mma.sync helpers ----------------
__device__ __forceinline__ void ldsm_x4(u32* r, u32 addr) {
    asm volatile("ldmatrix.sync.aligned.m8n8.x4.shared.b16 {%0,%1,%2,%3}, [%4];"
                 : "=r"(r[0]), "=r"(r[1]), "=r"(r[2]), "=r"(r[3]) : "r"(addr));
}
__device__ __forceinline__ void ldsm_x2t(u32* r, u32 addr) {
    asm volatile("ldmatrix.sync.aligned.m8n8.x2.trans.shared.b16 {%0,%1}, [%2];"
                 : "=r"(r[0]), "=r"(r[1]) : "r"(addr));
}
__device__ __forceinline__ void mma16816(float* c, const u32* a, const u32* b) {
    asm volatile("mma.sync.aligned.m16n8k16.row.col.f32.bf16.bf16.f32 "
                 "{%0,%1,%2,%3}, {%4,%5,%6,%7}, {%8,%9}, {%0,%1,%2,%3};"
                 : "+f"(c[0]), "+f"(c[1]), "+f"(c[2]), "+f"(c[3])
                 : "r"(a[0]), "r"(a[1]), "r"(a[2]), "r"(a[3]), "r"(b[0]), "r"(b[1]));
}
__device__ __forceinline__ void cp_async16(u32 dst, const void* src) {
    asm volatile("cp.async.cg.shared.global [%0], [%1], 16;" :: "r"(dst), "l"(src));
}
__device__ __forceinline__ void cp_async_wait_all() {
    asm volatile("cp.async.commit_group;");
    asm volatile("cp.async.wait_group 0;" ::: "memory");
}

// ---------------- device scratch ----------------
__device__ __align__(16) u32   g_xb[NN * 64];           // x packed bf16x2
__device__ __align__(16) u32   g_ob[NN * 64];           // o packed bf16x2
__device__ __align__(16) u32   g_hfb[NN * 256];         // GAT features bf16x2
__device__ __align__(16) u32   g_agg10b[(size_t)NL * NN * 64]; // E10 terms bf16x2
__device__ __align__(16) float g_x[NN * HD];
__device__ __align__(16) float g_eagg[NN * EDIM];
__device__           float g_u[NL * HD];
__device__           float g_degf[NN];
__device__           int   g_deg[NN];
__device__           int   g_rowptr[NN + 1];
__device__           int   g_cursor[NN];
__device__           int   g_csrc[NE];
__device__           int   g_ceid[NE];
__device__           int   g_bsum[64];
__device__           int   g_boff[64];
__device__ __align__(16) float g_as[NN * 4];
__device__ __align__(16) float g_ad[NN * 4];
__device__ __align__(16) float g_bnsum[HD];
__device__ __align__(16) float g_bnsq[HD];
__device__ __align__(16) float g_scale[HD];
__device__ __align__(16) float g_shift[HD];
__device__ __align__(16) float g_pool[NG * HD];

// Prepped weights: 0..9 WnW1[l], 20..29 W2[l], 30..39 V[l]=We@W1, 40..43 Wg blocks.
constexpr int NMAT = 44;
constexpr int WPAD = 136;
constexpr int WHALF = 128 * WPAD * 2;           // 34816
constexpr int WMAT_BYTES = 2 * WHALF;
__device__ __align__(16) char g_wb[(size_t)NMAT * WMAT_BYTES];

__device__ __forceinline__ void split_store(char* dst, int k, int n, float v) {
    __nv_bfloat16 h = __float2bfloat16(v);
    __nv_bfloat16 l = __float2bfloat16(v - __bfloat162float(h));
    ((__nv_bfloat16*)dst)[k * WPAD + n]           = h;
    ((__nv_bfloat16*)(dst + WHALF))[k * WPAD + n] = l;
}

// ---------------- weight prep ----------------
__global__ void prep_weights(const float* __restrict__ W2, const float* __restrict__ Wg) {
    int m = blockIdx.x;            // 0..13
    int slot = (m < 10) ? (20 + m) : (40 + (m - 10));
    char* dst = g_wb + (size_t)slot * WMAT_BYTES;
    for (int idx = threadIdx.x; idx < 16384; idx += blockDim.x) {
        int k = idx >> 7, n = idx & 127;
        float v = (m < 10) ? W2[(size_t)m * 16384 + k * 128 + n]
                           : Wg[(size_t)k * 512 + (m - 10) * 128 + n];
        split_store(dst, k, n, v);
    }
}
__global__ void comp_wnw1(const float* __restrict__ Wn, const float* __restrict__ W1) {
    extern __shared__ float s[];
    float* sA = s;
    float* sB = s + 16384;
    int l = blockIdx.x, tid = threadIdx.x;
    const float* A = Wn + (size_t)l * 16384;
    const float* B = W1 + (size_t)l * 16384;
    for (int i = tid; i < 16384; i += 256) { sA[i] = A[i]; sB[i] = B[i]; }
    __syncthreads();
    char* dst = g_wb + (size_t)l * WMAT_BYTES;
    int k = tid >> 1, c0 = (tid & 1) * 64;
    for (int n = c0; n < c0 + 64; n++) {
        float acc = 0.f;
#pragma unroll 8
        for (int m = 0; m < 128; m++) acc += sA[k * 128 + m] * sB[m * 128 + n];
        split_store(dst, k, n, acc);
    }
}
__global__ void comp_v(const float* __restrict__ We, const float* __restrict__ W1,
                       const float* __restrict__ bnb, const float* __restrict__ beb) {
    extern __shared__ float s[];
    float* sB  = s;
    float* sE  = s + 16384;
    float* sbb = s + 20480;
    int l = blockIdx.x, tid = threadIdx.x;
    const float* B = W1 + (size_t)l * 16384;
    const float* E = We + (size_t)l * 4096;
    for (int i = tid; i < 16384; i += 256) sB[i] = B[i];
    for (int i = tid; i < 4096; i += 256) sE[i] = E[i];
    if (tid < 128) sbb[tid] = bnb[l * 128 + tid] + beb[l * 128 + tid];
    __syncthreads();
    char* dst = g_wb + (size_t)(30 + l) * WMAT_BYTES;
    int k = tid >> 3, c0 = (tid & 7) * 16;
    for (int n = c0; n < c0 + 16; n++) {
        float acc = 0.f;
#pragma unroll 8
        for (int m = 0; m < 128; m++) acc += sE[k * 128 + m] * sB[m * 128 + n];
        split_store(dst, k, n, acc);
    }
    if (tid < 128) {
        float acc = 0.f;
#pragma unroll 8
        for (int m = 0; m < 128; m++) acc += sbb[m] * sB[m * 128 + tid];
        g_u[l * 128 + tid] = acc;
    }
}

// ---------------- SMEM layout for fused/GAT GEMMs ----------------
constexpr int AHALF = 64 * WPAD * 2;   // 17408 (single A buffer)
constexpr int SM_A  = 0;
constexpr int SM_BH = AHALF;           // 17408
constexpr int SM_BL = AHALF + WHALF;   // 52224
constexpr int SM_TOT = AHALF + 2 * WHALF;   // 87040 -> 2 CTAs/SM

// shared mainloop: 2 passes (Bh, Bl) over bf16 A at SM_A
__device__ __forceinline__ void run_mainloop(u32 sb, int wm, int wn, int lane,
                                             float acc[2][4][4]) {
#pragma unroll
    for (int i = 0; i < 2; i++)
#pragma unroll
        for (int j = 0; j < 4; j++)
#pragma unroll
            for (int q = 0; q < 4; q++) acc[i][j][q] = 0.f;
    const u32 boff[2] = { SM_BH, SM_BL };
#pragma unroll
    for (int p = 0; p < 2; p++) {
        u32 sa0 = sb + SM_A + ((wm * 32 + (lane & 15)) * WPAD + (lane >> 4) * 8) * 2;
        u32 sb0 = sb + boff[p] + ((lane & 15) * WPAD + wn * 32) * 2;
#pragma unroll
        for (int k = 0; k < 8; k++) {
            u32 af[2][4];
#pragma unroll
            for (int i = 0; i < 2; i++)
                ldsm_x4(af[i], sa0 + i * 16 * (WPAD * 2) + k * 32);
            u32 bf[4][2];
#pragma unroll
            for (int j = 0; j < 4; j++)
                ldsm_x2t(bf[j], sb0 + k * 16 * (WPAD * 2) + j * 16);
#pragma unroll
            for (int i = 0; i < 2; i++)
#pragma unroll
                for (int j = 0; j < 4; j++)
                    mma16816(acc[i][j], af[i], bf[j]);
        }
    }
}

// ---------------- fused layer: gather + t=relu(agg@WnW1 + E10 + b1); o = t@W2 + b2 ----------------
__global__ void __launch_bounds__(256, 2)
fused_layer(int l, const float* __restrict__ b1, const float* __restrict__ b2)
{
    extern __shared__ __align__(16) char smem[];
    u32 sb = smem_u32(smem);
    int tid = threadIdx.x, wid = tid >> 5, lane = tid & 31;
    int row0 = blockIdx.x * 64;
    int wm = wid >> 2, wn = wid & 3;

    // B <- WnW1[l] (hi+lo) async — overlaps the gather below
    {
        const char* src = g_wb + (size_t)l * WMAT_BYTES + tid * 16;
        u32 dst = sb + SM_BH + tid * 16;
#pragma unroll
        for (int i = 0; i < 17; i++)
            cp_async16(dst + i * 4096, src + i * 4096);
    }
    // A <- gather: agg[row] = sum over in-edges of x_bf16[src]; 4 threads per row
    {
        int r = tid >> 2, q = tid & 3;     // row, quarter (32 cols)
        int row = row0 + r;
        float acc[32];
#pragma unroll
        for (int i = 0; i < 32; i++) acc[i] = 0.f;
        if (row < NN) {
            int p0 = g_rowptr[row], p1 = g_rowptr[row + 1];
            const uint4* xbase = (const uint4*)g_xb;
            for (int p = p0; p < p1; p++) {
                int s = g_csrc[p];
                const uint4* xr = xbase + (size_t)s * 16 + q * 4;
#pragma unroll
                for (int i = 0; i < 4; i++) {
                    uint4 v = xr[i];
                    acc[i * 8 + 0] += bf_lo(v.x); acc[i * 8 + 1] += bf_hi(v.x);
                    acc[i * 8 + 2] += bf_lo(v.y); acc[i * 8 + 3] += bf_hi(v.y);
                    acc[i * 8 + 4] += bf_lo(v.z); acc[i * 8 + 5] += bf_hi(v.z);
                    acc[i * 8 + 6] += bf_lo(v.w); acc[i * 8 + 7] += bf_hi(v.w);
                }
            }
        }
        u32* AS = (u32*)(smem + SM_A) + ((r * WPAD + q * 32) >> 1);
#pragma unroll
        for (int i = 0; i < 16; i++)
            AS[i] = pack_bf2(acc[2 * i], acc[2 * i + 1]);
    }
    cp_async_wait_all();
    __syncthreads();

    float acc[2][4][4];
    run_mainloop(sb, wm, wn, lane, acc);
    __syncthreads();                       // everyone done with A and B

    // start W2 load while we write t into the A buffer
    {
        const char* src = g_wb + (size_t)(20 + l) * WMAT_BYTES + tid * 16;
        u32 dst = sb + SM_BH + tid * 16;
#pragma unroll
        for (int i = 0; i < 17; i++)
            cp_async16(dst + i * 4096, src + i * 4096);
    }
    // epilogue1: t = relu(acc + b1 + E10) -> SMEM A (bf16)
    {
        const u32* E = g_agg10b + (size_t)l * NN * 64;
#pragma unroll
        for (int i = 0; i < 2; i++) {
            int rl0 = wm * 32 + i * 16 + (lane >> 2);
#pragma unroll
            for (int half = 0; half < 2; half++) {
                int rloc = rl0 + half * 8;
                int row = row0 + rloc;
                bool valid = row < NN;
#pragma unroll
                for (int j = 0; j < 4; j++) {
                    int cc = wn * 32 + j * 8 + (lane & 3) * 2;
                    float v0 = 0.f, v1 = 0.f;
                    if (valid) {
                        u32 e = E[(size_t)row * 64 + (cc >> 1)];
                        v0 = fmaxf(acc[i][j][half * 2 + 0] + b1[cc]     + bf_lo(e), 0.f);
                        v1 = fmaxf(acc[i][j][half * 2 + 1] + b1[cc + 1] + bf_hi(e), 0.f);
                    }
                    *(u32*)(smem + SM_A + (rloc * WPAD + cc) * 2) = pack_bf2(v0, v1);
                }
            }
        }
    }
    cp_async_wait_all();
    __syncthreads();

    run_mainloop(sb, wm, wn, lane, acc);

    // epilogue2: o = acc + b2 -> bf16 g_ob, accumulate BN stats (fp32)
    float csum[8], csq[8];
#pragma unroll
    for (int q = 0; q < 8; q++) { csum[q] = 0.f; csq[q] = 0.f; }
#pragma unroll
    for (int i = 0; i < 2; i++) {
        int ra = row0 + wm * 32 + i * 16 + (lane >> 2);
#pragma unroll
        for (int half = 0; half < 2; half++) {
            int row = ra + half * 8;
            if (row < NN) {
#pragma unroll
                for (int j = 0; j < 4; j++) {
                    int cc = wn * 32 + j * 8 + (lane & 3) * 2;
                    float v0 = acc[i][j][half * 2 + 0] + b2[cc];
                    float v1 = acc[i][j][half * 2 + 1] + b2[cc + 1];
                    csum[j * 2]     += v0; csq[j * 2]     += v0 * v0;
                    csum[j * 2 + 1] += v1; csq[j * 2 + 1] += v1 * v1;
                    g_ob[(size_t)row * 64 + (cc >> 1)] = pack_bf2(v0, v1);
                }
            }
        }
    }
    {
        float* ssum = (float*)smem;
        float* ssq  = ssum + 128;
        __syncthreads();
        if (tid < 128) { ssum[tid] = 0.f; ssq[tid] = 0.f; }
        __syncthreads();
#pragma unroll
        for (int j = 0; j < 4; j++) {
#pragma unroll
            for (int c = 0; c < 2; c++) {
                int col = wn * 32 + j * 8 + (lane & 3) * 2 + c;
                atomicAdd(&ssum[col], csum[j * 2 + c]);
                atomicAdd(&ssq[col],  csq[j * 2 + c]);
            }
        }
        __syncthreads();
        if (tid < 128) {
            atomicAdd(&g_bnsum[tid], ssum[tid]);
            atomicAdd(&g_bnsq[tid],  ssq[tid]);
        }
    }
}

// ---------------- GAT GEMM: hfeat = normrelu(o_bf16) @ Wg -> bf16 ----------------
__global__ void __launch_bounds__(256, 2)
gat_gemm()
{
    extern __shared__ __align__(16) char smem[];
    u32 sb = smem_u32(smem);
    int tid = threadIdx.x, wid = tid >> 5, lane = tid & 31;
    int row0 = blockIdx.x * 64;
    int colb = blockIdx.y * 128;
    int wm = wid >> 2, wn = wid & 3;

    {
        const char* src = g_wb + (size_t)(40 + blockIdx.y) * WMAT_BYTES + tid * 16;
        u32 dst = sb + SM_BH + tid * 16;
#pragma unroll
        for (int i = 0; i < 17; i++)
            cp_async16(dst + i * 4096, src + i * 4096);
    }
    {
        int r = tid >> 2, cb = (tid & 3) * 32;
        bool valid = (row0 + r) < NN;
        u32* AS = (u32*)(smem + SM_A) + ((r * WPAD + cb) >> 1);
        const u32* arow = g_ob + (size_t)(row0 + r) * 64 + (cb >> 1);
#pragma unroll 8
        for (int i = 0; i < 16; i++) {
            u32 a = valid ? arow[i] : 0u;
            float2 sc = *(const float2*)&g_scale[cb + 2 * i];
            float2 sh = *(const float2*)&g_shift[cb + 2 * i];
            float v0 = fmaxf(bf_lo(a) * sc.x + sh.x, 0.f);
            float v1 = fmaxf(bf_hi(a) * sc.y + sh.y, 0.f);
            AS[i] = pack_bf2(v0, v1);
        }
    }
    cp_async_wait_all();
    __syncthreads();

    float acc[2][4][4];
    run_mainloop(sb, wm, wn, lane, acc);

#pragma unroll
    for (int i = 0; i < 2; i++) {
        int ra = row0 + wm * 32 + i * 16 + (lane >> 2);
#pragma unroll
        for (int half = 0; half < 2; half++) {
            int row = ra + half * 8;
            if (row < NN) {
#pragma unroll
                for (int j = 0; j < 4; j++) {
                    int cc = wn * 32 + j * 8 + (lane & 3) * 2;
                    float v0 = acc[i][j][half * 2 + 0];
                    float v1 = acc[i][j][half * 2 + 1];
                    g_hfb[(size_t)row * 256 + ((colb + cc) >> 1)] = pack_bf2(v0, v1);
                }
            }
        }
    }
}

// ---------------- batched E10 GEMM (2-pass): g_agg10b[l] = Eagg @ V[l] + deg*u[l] ----------------
constexpr int EPAD = 40;
constexpr int WE_A  = 0;
constexpr int WE_BH = 10240;
constexpr int WE_BL = 18944;
constexpr int WE_TOT = 27648;

__global__ void __launch_bounds__(256)
we_gemm()
{
    __shared__ __align__(16) char smem[WE_TOT];
    u32 sb = smem_u32(smem);
    int tid = threadIdx.x, wid = tid >> 5, lane = tid & 31;
    int row0 = blockIdx.x * 128;
    int l = blockIdx.y;

    {
        const char* mat = g_wb + (size_t)(30 + l) * WMAT_BYTES;
        for (int i = tid; i < 544; i += 256) {
            cp_async16(sb + WE_BH + i * 16, mat + i * 16);
            cp_async16(sb + WE_BL + i * 16, mat + WHALF + i * 16);
        }
    }
    {
        int r = tid >> 1, cb = (tid & 1) * 16;
        bool valid = (row0 + r) < NN;
        const float2* arow = (const float2*)(g_eagg + (size_t)(row0 + r) * 32 + cb);
        u32* AS = (u32*)(smem + WE_A) + ((r * EPAD + cb) >> 1);
#pragma unroll
        for (int i = 0; i < 8; i++) {
            float2 v = valid ? arow[i] : make_float2(0.f, 0.f);
            AS[i] = pack_bf2(v.x, v.y);
        }
    }
    cp_async_wait_all();
    __syncthreads();

    int wm = wid >> 2, wn = wid & 3;
    float acc[4][4][4];
#pragma unroll
    for (int i = 0; i < 4; i++)
#pragma unroll
        for (int j = 0; j < 4; j++)
#pragma unroll
            for (int q = 0; q < 4; q++) acc[i][j][q] = 0.f;

    const u32 boff[2] = { WE_BH, WE_BL };
#pragma unroll
    for (int p = 0; p < 2; p++) {
        u32 sa0 = sb + WE_A + ((wm * 64 + (lane & 15)) * EPAD + (lane >> 4) * 8) * 2;
        u32 sb0 = sb + boff[p] + ((lane & 15) * WPAD + wn * 32) * 2;
#pragma unroll
        for (int k = 0; k < 2; k++) {
            u32 af[4][4];
#pragma unroll
            for (int i = 0; i < 4; i++)
                ldsm_x4(af[i], sa0 + i * 16 * (EPAD * 2) + k * 32);
            u32 bf[4][2];
#pragma unroll
            for (int j = 0; j < 4; j++)
                ldsm_x2t(bf[j], sb0 + k * 16 * (WPAD * 2) + j * 16);
#pragma unroll
            for (int i = 0; i < 4; i++)
#pragma unroll
                for (int j = 0; j < 4; j++)
                    mma16816(acc[i][j], af[i], bf[j]);
        }
    }

    u32* C = g_agg10b + (size_t)l * NN * 64;
    const float* bias = g_u + l * HD;
#pragma unroll
    for (int i = 0; i < 4; i++) {
        int ra = row0 + wm * 64 + i * 16 + (lane >> 2);
#pragma unroll
        for (int half = 0; half < 2; half++) {
            int row = ra + half * 8;
            if (row < NN) {
                float rs = g_degf[row];
#pragma unroll
                for (int j = 0; j < 4; j++) {
                    int cc = wn * 32 + j * 8 + (lane & 3) * 2;
                    float v0 = acc[i][j][half * 2 + 0] + rs * bias[cc];
                    float v1 = acc[i][j][half * 2 + 1] + rs * bias[cc + 1];
                    C[(size_t)row * 64 + (cc >> 1)] = pack_bf2(v0, v1);
                }
            }
        }
    }
}

// ---------------- CSR build ----------------
__global__ void zero_deg() {
    int i = blockIdx.x * blockDim.x + threadIdx.x;
    if (i < NN) g_deg[i] = 0;
    if (i < HD) { g_bnsum[i] = 0.f; g_bnsq[i] = 0.f; }
}
__global__ void hist_kernel(const int* __restrict__ ei) {
    int e = blockIdx.x * blockDim.x + threadIdx.x;
    if (e < NE) atomicAdd(&g_deg[ei[NE + e]], 1);
}
__global__ void scan_blocks() {
    __shared__ int wsum[32];
    int tid = threadIdx.x, lane = tid & 31, w = tid >> 5;
    int i = blockIdx.x * 1024 + tid;
    int v = (i < NN) ? g_deg[i] : 0;
    int x = v;
#pragma unroll
    for (int o = 1; o < 32; o <<= 1) { int t = __shfl_up_sync(~0u, x, o); if (lane >= o) x += t; }
    if (lane == 31) wsum[w] = x;
    __syncthreads();
    if (w == 0) {
        int s = wsum[lane];
#pragma unroll
        for (int o = 1; o < 32; o <<= 1) { int t = __shfl_up_sync(~0u, s, o); if (lane >= o) s += t; }
        wsum[lane] = s;
    }
    __syncthreads();
    int wexcl = (w == 0) ? 0 : wsum[w - 1];
    if (i < NN) g_rowptr[i] = wexcl + x - v;
    if (tid == 1023) g_bsum[blockIdx.x] = wsum[31];
}
__global__ void scan_tops() {
    int tid = threadIdx.x;
    __shared__ int sh[64];
    __shared__ int w0tot;
    int v = (tid < 49) ? g_bsum[tid] : 0;
    int lane = tid & 31, w = tid >> 5;
    int x = v;
#pragma unroll
    for (int o = 1; o < 32; o <<= 1) { int t = __shfl_up_sync(~0u, x, o); if (lane >= o) x += t; }
    if (w == 0 && lane == 31) w0tot = x;
    __syncthreads();
    int incl = x + (w == 1 ? w0tot : 0);
    sh[tid] = incl - v;
    __syncthreads();
    if (tid < 49) g_boff[tid] = sh[tid];
}
__global__ void scan_apply() {
    int i = blockIdx.x * blockDim.x + threadIdx.x;
    if (i >= NN) return;
    int rp = g_rowptr[i] + g_boff[i >> 10];
    g_rowptr[i] = rp;
    g_cursor[i] = rp;
    g_degf[i]   = (float)g_deg[i];
    if (i == 0) g_rowptr[NN] = NE;
}
__global__ void scatter_kernel(const int* __restrict__ ei) {
    int e = blockIdx.x * blockDim.x + threadIdx.x;
    if (e >= NE) return;
    int s = ei[e], d = ei[NE + e];
    int p = atomicAdd(&g_cursor[d], 1);
    g_csrc[p] = s;
    g_ceid[p] = e;
}
__global__ void eagg_kernel(const float* __restrict__ edge_attr) {
    int w = (blockIdx.x * blockDim.x + threadIdx.x) >> 5;
    if (w >= NN) return;
    int lane = threadIdx.x & 31;
    float acc = 0.f;
    int p0 = g_rowptr[w], p1 = g_rowptr[w + 1];
    for (int p = p0; p < p1; p++) {
        int e = g_ceid[p];
        acc += edge_attr[e * EDIM + lane];
    }
    g_eagg[w * EDIM + lane] = acc;
}

// ---------------- conversions ----------------
__global__ void cvt_x(const float* __restrict__ x) {
    int i = blockIdx.x * blockDim.x + threadIdx.x;
    if (i >= NN * 64) return;
    float2 v = ((const float2*)x)[i];
    g_xb[i] = pack_bf2(v.x, v.y);
}
__global__ void normrelu_bf16() {
    int i = blockIdx.x * blockDim.x + threadIdx.x;
    if (i >= NN * 64) return;
    u32 v = g_ob[i];
    int c = i & 63;
    float2 sc = ((const float2*)g_scale)[c];
    float2 sh = ((const float2*)g_shift)[c];
    float a = fmaxf(bf_lo(v) * sc.x + sh.x, 0.f);
    float b = fmaxf(bf_hi(v) * sc.y + sh.y, 0.f);
    g_xb[i] = pack_bf2(a, b);
}

// ---------------- BatchNorm scalars (self-resetting) ----------------
__global__ void bn_final(const float* __restrict__ gamma, const float* __restrict__ beta) {
    int c = threadIdx.x;
    if (c >= HD) return;
    float su = g_bnsum[c], sq = g_bnsq[c];
    g_bnsum[c] = 0.f;
    g_bnsq[c]  = 0.f;
    float mu  = su / (float)NN;
    float var = sq / (float)NN - mu * mu;
    float sc  = gamma[c] * rsqrtf(var + EPSF);
    g_scale[c] = sc;
    g_shift[c] = beta[c] - mu * sc;
}

// ---------------- GAT ----------------
__global__ void gat_node1(const float* __restrict__ att_src, const float* __restrict__ att_dst) {
    int n = (blockIdx.x * blockDim.x + threadIdx.x) >> 5;
    if (n >= NN) return;
    int lane = threadIdx.x & 31;
    float s[4], d[4];
#pragma unroll
    for (int h = 0; h < 4; h++) {
        uint2 hp = *(const uint2*)&g_hfb[(size_t)n * 256 + h * 64 + lane * 2];
        float4 hv = { bf_lo(hp.x), bf_hi(hp.x), bf_lo(hp.y), bf_hi(hp.y) };
        float4 a1 = *(const float4*)&att_src[h * 128 + lane * 4];
        float4 a2 = *(const float4*)&att_dst[h * 128 + lane * 4];
        float ps = hv.x * a1.x + hv.y * a1.y + hv.z * a1.z + hv.w * a1.w;
        float pd = hv.x * a2.x + hv.y * a2.y + hv.z * a2.z + hv.w * a2.w;
#pragma unroll
        for (int off = 16; off > 0; off >>= 1) {
            ps += __shfl_xor_sync(0xffffffffu, ps, off);
            pd += __shfl_xor_sync(0xffffffffu, pd, off);
        }
        s[h] = ps; d[h] = pd;
    }
    if (lane == 0) {
#pragma unroll
        for (int h = 0; h < 4; h++) {
            g_as[n * 4 + h] = s[h];
            g_ad[n * 4 + h] = d[h];
        }
    }
}
__global__ void gat_node_all(const float* __restrict__ bg) {
    int n = (blockIdx.x * blockDim.x + threadIdx.x) >> 5;
    if (n >= NN) return;
    int lane = threadIdx.x & 31;
    float4 asn = *(const float4*)&g_as[n * 4];
    float4 adn = *(const float4*)&g_ad[n * 4];
    float sl0 = lrelu(asn.x + adn.x), sl1 = lrelu(asn.y + adn.y);
    float sl2 = lrelu(asn.z + adn.z), sl3 = lrelu(asn.w + adn.w);
    int p0 = g_rowptr[n], p1 = g_rowptr[n + 1];

    float m0 = sl0, m1 = sl1, m2 = sl2, m3 = sl3;
    for (int p = p0 + lane; p < p1; p += 32) {
        float4 a = *(const float4*)&g_as[g_csrc[p] * 4];
        m0 = fmaxf(m0, lrelu(a.x + adn.x)); m1 = fmaxf(m1, lrelu(a.y + adn.y));
        m2 = fmaxf(m2, lrelu(a.z + adn.z)); m3 = fmaxf(m3, lrelu(a.w + adn.w));
    }
#pragma unroll
    for (int o = 16; o > 0; o >>= 1) {
        m0 = fmaxf(m0, __shfl_xor_sync(~0u, m0, o));
        m1 = fmaxf(m1, __shfl_xor_sync(~0u, m1, o));
        m2 = fmaxf(m2, __shfl_xor_sync(~0u, m2, o));
        m3 = fmaxf(m3, __shfl_xor_sync(~0u, m3, o));
    }
    float d0 = 0.f, d1 = 0.f, d2 = 0.f, d3 = 0.f;
    for (int p = p0 + lane; p < p1; p += 32) {
        float4 a = *(const float4*)&g_as[g_csrc[p] * 4];
        d0 += __expf(lrelu(a.x + adn.x) - m0); d1 += __expf(lrelu(a.y + adn.y) - m1);
        d2 += __expf(lrelu(a.z + adn.z) - m2); d3 += __expf(lrelu(a.w + adn.w) - m3);
    }
#pragma unroll
    for (int o = 16; o > 0; o >>= 1) {
        d0 += __shfl_xor_sync(~0u, d0, o); d1 += __shfl_xor_sync(~0u, d1, o);
        d2 += __shfl_xor_sync(~0u, d2, o); d3 += __shfl_xor_sync(~0u, d3, o);
    }
    d0 += __expf(sl0 - m0); d1 += __expf(sl1 - m1);
    d2 += __expf(sl2 - m2); d3 += __expf(sl3 - m3);
    float i0 = 1.f / d0, i1 = 1.f / d1, i2 = 1.f / d2, i3 = 1.f / d3;

    float w0 = __expf(sl0 - m0) * i0, w1 = __expf(sl1 - m1) * i1;
    float w2 = __expf(sl2 - m2) * i2, w3 = __expf(sl3 - m3) * i3;
    size_t base = (size_t)n * 256 + lane * 2;
    uint2 hp0 = *(const uint2*)&g_hfb[base];
    uint2 hp1 = *(const uint2*)&g_hfb[base + 64];
    uint2 hp2 = *(const uint2*)&g_hfb[base + 128];
    uint2 hp3 = *(const uint2*)&g_hfb[base + 192];
    float4 A0 = { w0 * bf_lo(hp0.x), w0 * bf_hi(hp0.x), w0 * bf_lo(hp0.y), w0 * bf_hi(hp0.y) };
    float4 A1 = { w1 * bf_lo(hp1.x), w1 * bf_hi(hp1.x), w1 * bf_lo(hp1.y), w1 * bf_hi(hp1.y) };
    float4 A2 = { w2 * bf_lo(hp2.x), w2 * bf_hi(hp2.x), w2 * bf_lo(hp2.y), w2 * bf_hi(hp2.y) };
    float4 A3 = { w3 * bf_lo(hp3.x), w3 * bf_hi(hp3.x), w3 * bf_lo(hp3.y), w3 * bf_hi(hp3.y) };
    for (int p = p0; p < p1; p++) {
        int s = g_csrc[p];
        float4 a = *(const float4*)&g_as[s * 4];
        float e0 = __expf(lrelu(a.x + adn.x) - m0) * i0;
        float e1 = __expf(lrelu(a.y + adn.y) - m1) * i1;
        float e2 = __expf(lrelu(a.z + adn.z) - m2) * i2;
        float e3 = __expf(lrelu(a.w + adn.w) - m3) * i3;
        size_t sbx = (size_t)s * 256 + lane * 2;
        uint2 v0 = *(const uint2*)&g_hfb[sbx];
        uint2 v1 = *(const uint2*)&g_hfb[sbx + 64];
        uint2 v2 = *(const uint2*)&g_hfb[sbx + 128];
        uint2 v3 = *(const uint2*)&g_hfb[sbx + 192];
        A0.x += e0 * bf_lo(v0.x); A0.y += e0 * bf_hi(v0.x); A0.z += e0 * bf_lo(v0.y); A0.w += e0 * bf_hi(v0.y);
        A1.x += e1 * bf_lo(v1.x); A1.y += e1 * bf_hi(v1.x); A1.z += e1 * bf_lo(v1.y); A1.w += e1 * bf_hi(v1.y);
        A2.x += e2 * bf_lo(v2.x); A2.y += e2 * bf_hi(v2.x); A2.z += e2 * bf_lo(v2.y); A2.w += e2 * bf_hi(v2.y);
        A3.x += e3 * bf_lo(v3.x); A3.y += e3 * bf_hi(v3.x); A3.z += e3 * bf_lo(v3.y); A3.w += e3 * bf_hi(v3.y);
    }
    float4 bg4 = *(const float4*)&bg[lane * 4];
    float4 o4;
    o4.x = (A0.x + A1.x + A2.x + A3.x) * 0.25f + bg4.x;
    o4.y = (A0.y + A1.y + A2.y + A3.y) * 0.25f + bg4.y;
    o4.z = (A0.z + A1.z + A2.z + A3.z) * 0.25f + bg4.z;
    o4.w = (A0.w + A1.w + A2.w + A3.w) * 0.25f + bg4.w;
    *(float4*)&g_x[(size_t)n * HD + lane * 4] = o4;
}

// ---------------- pooling + fc ----------------
__device__ __forceinline__ int lbound(const int* a, int n, int key) {
    int lo = 0, hi = n;
    while (lo < hi) { int mid = (lo + hi) >> 1; if (a[mid] < key) lo = mid + 1; else hi = mid; }
    return lo;
}
__global__ void pool_kernel(const int* __restrict__ batch) {
    int g = blockIdx.x;
    int c = threadIdx.x;
    __shared__ int slo, shi;
    if (c == 0) { slo = lbound(batch, NN, g); shi = lbound(batch, NN, g + 1); }
    __syncthreads();
    int lo = slo, hi = shi;
    float a0 = 0.f, a1 = 0.f, a2 = 0.f, a3 = 0.f;
    int n = lo;
    for (; n + 4 <= hi; n += 4) {
        a0 += g_x[(size_t)n * HD + c];
        a1 += g_x[(size_t)(n + 1) * HD + c];
        a2 += g_x[(size_t)(n + 2) * HD + c];
        a3 += g_x[(size_t)(n + 3) * HD + c];
    }
    for (; n < hi; n++) a0 += g_x[(size_t)n * HD + c];
    float s = (a0 + a1) + (a2 + a3);
    g_pool[g * HD + c] = s / fmaxf((float)(hi - lo), 1.f);
}
__global__ void final_kernel(const float* __restrict__ Wfc, const float* __restrict__ bfc,
                             float* __restrict__ out) {
    int idx = blockIdx.x * blockDim.x + threadIdx.x;
    if (idx >= NG * NOUT) return;
    int g = idx / NOUT, o = idx % NOUT;
    float s = bfc[o];
#pragma unroll 8
    for (int k = 0; k < HD; k++) s += g_pool[g * HD + k] * Wfc[k * NOUT + o];
    out[idx] = s;
}

// ---------------- driver ----------------
extern "C" void kernel_launch(void* const* d_in, const int* in_sizes, int n_in,
                              void* d_out, int out_size) {
    const float* x_in      = (const float*)d_in[0];
    const float* edge_attr = (const float*)d_in[1];
    const int*   ei        = (const int*)d_in[2];
    const int*   batch     = (const int*)d_in[3];
    const float* Wn   = (const float*)d_in[4];
    const float* bn_b = (const float*)d_in[5];
    const float* We   = (const float*)d_in[6];
    const float* be_b = (const float*)d_in[7];
    const float* W1   = (const float*)d_in[8];
    const float* b1   = (const float*)d_in[9];
    const float* W2   = (const float*)d_in[10];
    const float* b2   = (const float*)d_in[11];
    const float* gamma= (const float*)d_in[12];
    const float* beta = (const float*)d_in[13];
    const float* Wg   = (const float*)d_in[14];
    const float* att_src = (const float*)d_in[15];
    const float* att_dst = (const float*)d_in[16];
    const float* bg   = (const float*)d_in[17];
    const float* Wfc  = (const float*)d_in[18];
    const float* bfc  = (const float*)d_in[19];
    float* out = (float*)d_out;

    cudaFuncSetAttribute(fused_layer, cudaFuncAttributeMaxDynamicSharedMemorySize, SM_TOT);
    cudaFuncSetAttribute(gat_gemm,    cudaFuncAttributeMaxDynamicSharedMemorySize, SM_TOT);
    cudaFuncSetAttribute(comp_wnw1, cudaFuncAttributeMaxDynamicSharedMemorySize, 131072);
    cudaFuncSetAttribute(comp_v,    cudaFuncAttributeMaxDynamicSharedMemorySize, 83968);

    const int TB = 256;
    const int NODE_BLK = (NN + TB - 1) / TB;
    const int EDGE_BLK = (NE + TB - 1) / TB;
    const int WARP_BLK = (NN * 32 + TB - 1) / TB;
    const int VEC_BLK  = (NN * 64 + TB - 1) / TB;
    const dim3 GEMM_G(782, 1);
    const dim3 GEMM_G4(782, 4);

    // prologue
    prep_weights<<<14, 256>>>(W2, Wg);
    comp_wnw1<<<10, 256, 131072>>>(Wn, W1);
    comp_v<<<10, 256, 83968>>>(We, W1, bn_b, be_b);
    cvt_x<<<VEC_BLK, TB>>>(x_in);
    zero_deg<<<NODE_BLK, TB>>>();
    hist_kernel<<<EDGE_BLK, TB>>>(ei);
    scan_blocks<<<49, 1024>>>();
    scan_tops<<<1, 64>>>();
    scan_apply<<<NODE_BLK, TB>>>();
    scatter_kernel<<<EDGE_BLK, TB>>>(ei);
    eagg_kernel<<<WARP_BLK, TB>>>(edge_attr);
    we_gemm<<<dim3(391, 10), 256>>>();

    // ---- 10 GINE layers (gather fused into the layer kernel) ----
    for (int l = 0; l < NL; l++) {
        if (l > 0) normrelu_bf16<<<VEC_BLK, TB>>>();
        fused_layer<<<GEMM_G, 256, SM_TOT>>>(l, b1 + l * HD, b2 + l * HD);
        bn_final<<<1, 128>>>(gamma + l * HD, beta + l * HD);
    }

    // ---- GAT (A = g_ob with layer-9 norm+relu applied in-load) ----
    gat_gemm<<<GEMM_G4, 256, SM_TOT>>>();
    gat_node1<<<WARP_BLK, TB>>>(att_src, att_dst);
    gat_node_all<<<WARP_BLK, TB>>>(bg);

    // ---- pool + fc ----
    pool_kernel<<<NG, 128>>>(batch);
    final_kernel<<<(NG * NOUT + TB - 1) / TB, TB>>>(Wfc, bfc, out);
}